// round 2
// baseline (speedup 1.0000x reference)
#include <cuda_runtime.h>
#include <cstdint>
#include <cstddef>

#define NB 8
#define NC 512
#define NIC 64
#define NH 96
#define NHW 9216

// ---------------- scratch (device globals; no runtime allocation) ----------
__device__ float g_q [NB*NIC*NHW];
__device__ float g_k [NB*NIC*NHW];
__device__ float g_qt[NB*NIC*NHW];
__device__ float g_kt[NB*NIC*NHW];
__device__ float g_Ew[(size_t)NB*NHW*96];   // [b][h][w][v] row logits -> A_w
__device__ float g_Eh[(size_t)NB*NHW*96];   // [b][w][h][g] col logits -> A_h^T
__device__ float g_xt[(size_t)NB*NC*NHW];   // x with h<->w swapped
__device__ float g_y [(size_t)NB*NC*NHW];
__device__ float g_yt[(size_t)NB*NC*NHW];

// ---------------- helpers ---------------------------------------------------
__device__ __forceinline__ float tf32r(float v){
  unsigned u; asm("cvt.rna.tf32.f32 %0,%1;":"=r"(u):"f"(v)); return __uint_as_float(u);
}
__device__ __forceinline__ void mma8(float* d, const unsigned* a, const unsigned* b){
  asm volatile("mma.sync.aligned.m16n8k8.row.col.f32.tf32.tf32.f32 "
    "{%0,%1,%2,%3},{%4,%5,%6,%7},{%8,%9},{%0,%1,%2,%3};\n"
    :"+f"(d[0]),"+f"(d[1]),"+f"(d[2]),"+f"(d[3])
    :"r"(a[0]),"r"(a[1]),"r"(a[2]),"r"(a[3]),"r"(b[0]),"r"(b[1]));
}

// ---------------- batched 96x96 transpose (optionally accumulating) --------
__global__ __launch_bounds__(256) void transpose96(const float* __restrict__ xin, int mode){
  __shared__ float s[96][97];
  const float* in; float* out; bool add=false;
  if(mode==0){in=xin;  out=g_xt;}
  else if(mode==1){in=g_q;  out=g_qt;}
  else if(mode==2){in=g_k;  out=g_kt;}
  else        {in=g_yt; out=g_y; add=true;}
  size_t base=(size_t)blockIdx.x*NHW;
  int t=threadIdx.x;
#pragma unroll
  for(int i=0;i<36;i++){int idx=t+i*256; s[idx/96][idx%96]=in[base+idx];}
  __syncthreads();
#pragma unroll
  for(int i=0;i<36;i++){int idx=t+i*256; float v=s[idx%96][idx/96];
    out[base+idx]= add ? out[base+idx]+v : v;}
}

// ---------------- q/k projection: [Wq;Wk](128x512) @ x_b, split-tf32 -------
__global__ __launch_bounds__(256) void gemm_qk(const float* __restrict__ x,
  const float* __restrict__ Wq, const float* __restrict__ bq,
  const float* __restrict__ Wk, const float* __restrict__ bk)
{
  __shared__ float Ah[16][136], Al[16][136], Bh[16][136], Bl[16][136];
  const int bI=blockIdx.y, n0=blockIdx.x*128;
  const float* Bp = x + (size_t)bI*NC*NHW;
  const int t=threadIdx.x, lane=t&31, grp=lane>>2, tig=lane&3;
  const int warp=t>>5, wm=warp>>2, wn=warp&3;

  float acc[4][4][4];
#pragma unroll
  for(int i=0;i<4;i++)for(int j=0;j<4;j++)for(int r=0;r<4;r++) acc[i][j][r]=0.f;

  const int am=t&127, ak=(t>>7)*8;
  const float* Ar = (am<64)? Wq+(size_t)am*NC : Wk+(size_t)(am-64)*NC;
  const int bn=t&127, bk0=t>>7;

  for(int k0=0;k0<NC;k0+=16){
    float av[8];
    *(float4*)(av)   = *(const float4*)(Ar+k0+ak);
    *(float4*)(av+4) = *(const float4*)(Ar+k0+ak+4);
    float bv8[8];
#pragma unroll
    for(int i=0;i<8;i++) bv8[i]=Bp[(size_t)(k0+bk0+2*i)*NHW + n0+bn];
    if(k0) __syncthreads();
#pragma unroll
    for(int i=0;i<8;i++){float h=tf32r(av[i]); Ah[ak+i][am]=h; Al[ak+i][am]=tf32r(av[i]-h);}
#pragma unroll
    for(int i=0;i<8;i++){float h=tf32r(bv8[i]); Bh[bk0+2*i][bn]=h; Bl[bk0+2*i][bn]=tf32r(bv8[i]-h);}
    __syncthreads();
#pragma unroll
    for(int ks=0;ks<16;ks+=8){
      unsigned ah[4][4], al[4][4], bh[4][2], bl[4][2];
#pragma unroll
      for(int mt=0;mt<4;mt++){
        int mb=wm*64+mt*16;
        ah[mt][0]=__float_as_uint(Ah[ks+tig][mb+grp]);
        ah[mt][1]=__float_as_uint(Ah[ks+tig][mb+grp+8]);
        ah[mt][2]=__float_as_uint(Ah[ks+tig+4][mb+grp]);
        ah[mt][3]=__float_as_uint(Ah[ks+tig+4][mb+grp+8]);
        al[mt][0]=__float_as_uint(Al[ks+tig][mb+grp]);
        al[mt][1]=__float_as_uint(Al[ks+tig][mb+grp+8]);
        al[mt][2]=__float_as_uint(Al[ks+tig+4][mb+grp]);
        al[mt][3]=__float_as_uint(Al[ks+tig+4][mb+grp+8]);
      }
#pragma unroll
      for(int nt=0;nt<4;nt++){
        int nb=wn*32+nt*8;
        bh[nt][0]=__float_as_uint(Bh[ks+tig][nb+grp]);
        bh[nt][1]=__float_as_uint(Bh[ks+tig+4][nb+grp]);
        bl[nt][0]=__float_as_uint(Bl[ks+tig][nb+grp]);
        bl[nt][1]=__float_as_uint(Bl[ks+tig+4][nb+grp]);
      }
#pragma unroll
      for(int mt=0;mt<4;mt++)
#pragma unroll
        for(int nt=0;nt<4;nt++){
          mma8(acc[mt][nt], ah[mt], bh[nt]);
          mma8(acc[mt][nt], al[mt], bh[nt]);
          mma8(acc[mt][nt], ah[mt], bl[nt]);
        }
    }
  }
#pragma unroll
  for(int mt=0;mt<4;mt++)
#pragma unroll
    for(int half=0;half<2;half++){
      int rr=wm*64+mt*16+grp+half*8;
      float bias; float* dst;
      if(rr<64){bias=bq[rr]; dst=g_q+((size_t)bI*NIC+rr)*NHW;}
      else     {bias=bk[rr-64]; dst=g_k+((size_t)bI*NIC+(rr-64))*NHW;}
#pragma unroll
      for(int nt=0;nt<4;nt++){
        int cc=n0+wn*32+nt*8+tig*2;
        float2 v; v.x=acc[mt][nt][half*2]+bias; v.y=acc[mt][nt][half*2+1]+bias;
        *(float2*)(dst+cc)=v;
      }
    }
}

// ---------------- logits: per (b,slab) 96x96 = Q^T K over 64 ch, split-tf32
__global__ __launch_bounds__(256) void logits_kernel(){
  __shared__ float Qh[16][104], Ql[16][104], Kh[16][104], Kl[16][104];
  const int slab=blockIdx.x, mode=blockIdx.y;
  const int bI=slab/96, s=slab%96;
  const float* Qp=(mode? g_qt : g_q) + (size_t)bI*NIC*NHW + s*96;
  const float* Kp=(mode? g_kt : g_k) + (size_t)bI*NIC*NHW + s*96;
  float* Ep=(mode? g_Eh : g_Ew) + (size_t)slab*NHW;
  const int t=threadIdx.x, lane=t&31, grp=lane>>2, tig=lane&3;
  const int warp=t>>5, wm=warp>>2, wn=warp&3;   // 2 x 4 warps; tile 48 x 24

  float acc[3][3][4];
#pragma unroll
  for(int i=0;i<3;i++)for(int j=0;j<3;j++)for(int r=0;r<4;r++) acc[i][j][r]=0.f;

  for(int c0=0;c0<NIC;c0+=16){
    if(c0) __syncthreads();
#pragma unroll
    for(int i=0;i<6;i++){
      int idx=t+i*256, cl=idx/96, w=idx%96;
      float qv=Qp[(size_t)(c0+cl)*NHW + w];
      float kv=Kp[(size_t)(c0+cl)*NHW + w];
      float qh=tf32r(qv), kh=tf32r(kv);
      Qh[cl][w]=qh; Ql[cl][w]=tf32r(qv-qh);
      Kh[cl][w]=kh; Kl[cl][w]=tf32r(kv-kh);
    }
    __syncthreads();
#pragma unroll
    for(int ks=0;ks<16;ks+=8){
      unsigned ah[3][4], al[3][4], bh[3][2], bl[3][2];
#pragma unroll
      for(int mt=0;mt<3;mt++){
        int mb=wm*48+mt*16;
        ah[mt][0]=__float_as_uint(Qh[ks+tig][mb+grp]);
        ah[mt][1]=__float_as_uint(Qh[ks+tig][mb+grp+8]);
        ah[mt][2]=__float_as_uint(Qh[ks+tig+4][mb+grp]);
        ah[mt][3]=__float_as_uint(Qh[ks+tig+4][mb+grp+8]);
        al[mt][0]=__float_as_uint(Ql[ks+tig][mb+grp]);
        al[mt][1]=__float_as_uint(Ql[ks+tig][mb+grp+8]);
        al[mt][2]=__float_as_uint(Ql[ks+tig+4][mb+grp]);
        al[mt][3]=__float_as_uint(Ql[ks+tig+4][mb+grp+8]);
      }
#pragma unroll
      for(int nt=0;nt<3;nt++){
        int nb=wn*24+nt*8;
        bh[nt][0]=__float_as_uint(Kh[ks+tig][nb+grp]);
        bh[nt][1]=__float_as_uint(Kh[ks+tig+4][nb+grp]);
        bl[nt][0]=__float_as_uint(Kl[ks+tig][nb+grp]);
        bl[nt][1]=__float_as_uint(Kl[ks+tig+4][nb+grp]);
      }
#pragma unroll
      for(int mt=0;mt<3;mt++)
#pragma unroll
        for(int nt=0;nt<3;nt++){
          mma8(acc[mt][nt], ah[mt], bh[nt]);
          mma8(acc[mt][nt], al[mt], bh[nt]);
          mma8(acc[mt][nt], ah[mt], bl[nt]);
        }
    }
  }
#pragma unroll
  for(int mt=0;mt<3;mt++)
#pragma unroll
    for(int half=0;half<2;half++){
      int row=wm*48+mt*16+grp+half*8;
#pragma unroll
      for(int nt=0;nt<3;nt++){
        int col=wn*24+nt*8+tig*2;
        float2 v; v.x=acc[mt][nt][half*2]; v.y=acc[mt][nt][half*2+1];
        *(float2*)(Ep+(size_t)row*96+col)=v;
      }
    }
}

// ---------------- fused 192-wide softmax (in place), diag mask on e_h ------
__global__ __launch_bounds__(256) void softmax_kernel(){
  const int warp=threadIdx.x>>5, lane=threadIdx.x&31;
  const int p=blockIdx.x*8+warp;
  const int bI=p/NHW, rem=p%NHW, h=rem/96, w=rem%96;
  float* ehp = g_Eh + ((size_t)(bI*96+w)*96 + h)*96;
  float* ewp = g_Ew + (size_t)p*96;
  float eh[3], ew[3], m=-1e30f;
#pragma unroll
  for(int j=0;j<3;j++){
    int g=lane+32*j;
    eh[j]=(g==h)? -1e30f : ehp[g];
    ew[j]=ewp[g];
    m=fmaxf(m,fmaxf(eh[j],ew[j]));
  }
#pragma unroll
  for(int o=16;o>0;o>>=1) m=fmaxf(m,__shfl_xor_sync(0xffffffffu,m,o));
  float sum=0.f;
#pragma unroll
  for(int j=0;j<3;j++){
    eh[j]=__expf(eh[j]-m); ew[j]=__expf(ew[j]-m); sum+=eh[j]+ew[j];
  }
#pragma unroll
  for(int o=16;o>0;o>>=1) sum+=__shfl_xor_sync(0xffffffffu,sum,o);
  float inv=1.f/sum;
#pragma unroll
  for(int j=0;j<3;j++){
    int g=lane+32*j;
    ehp[g]=(g==h)?0.f:eh[j]*inv;
    ewp[g]=ew[j]*inv;
  }
}

// ---------------- aggregation: y[c][n] = sum_k X[c][k]*Wt[n][k], tf32 ------
__global__ __launch_bounds__(256) void agg_kernel(const float* __restrict__ x){
  __shared__ float Xs[32][136], Ws[32][104];
  const int m0=blockIdx.x*128, slab=blockIdx.y, mode=blockIdx.z;
  const int bI=slab/96, s=slab%96;
  const float* Xp=(mode? g_xt : x) + (size_t)bI*NC*NHW + s*96;
  const float* Wt=(mode? g_Eh : g_Ew) + (size_t)slab*NHW;  // [n][k] 96x96
  float* Yp=(mode? g_yt : g_y) + (size_t)bI*NC*NHW + s*96;
  const int t=threadIdx.x, lane=t&31, grp=lane>>2, tig=lane&3;
  const int warp=t>>5, wm=warp>>1, wn=warp&1;  // 4 x 2 warps; tile 32 x 48

  float acc[2][6][4];
#pragma unroll
  for(int i=0;i<2;i++)for(int j=0;j<6;j++)for(int r=0;r<4;r++) acc[i][j][r]=0.f;

  for(int k0=0;k0<96;k0+=32){
    if(k0) __syncthreads();
#pragma unroll
    for(int i=0;i<16;i++){
      int idx=t+i*256, kk=idx&31, c=idx>>5;
      Xs[kk][c]=tf32r(Xp[(size_t)(m0+c)*NHW + k0+kk]);
    }
#pragma unroll
    for(int i=0;i<12;i++){
      int idx=t+i*256, kk=idx&31, n=idx>>5;
      Ws[kk][n]=tf32r(Wt[(size_t)n*96 + k0+kk]);
    }
    __syncthreads();
#pragma unroll
    for(int ks=0;ks<32;ks+=8){
      unsigned af[2][4], bf[6][2];
#pragma unroll
      for(int mt=0;mt<2;mt++){
        int mb=wm*32+mt*16;
        af[mt][0]=__float_as_uint(Xs[ks+tig][mb+grp]);
        af[mt][1]=__float_as_uint(Xs[ks+tig][mb+grp+8]);
        af[mt][2]=__float_as_uint(Xs[ks+tig+4][mb+grp]);
        af[mt][3]=__float_as_uint(Xs[ks+tig+4][mb+grp+8]);
      }
#pragma unroll
      for(int nt=0;nt<6;nt++){
        int nb=wn*48+nt*8;
        bf[nt][0]=__float_as_uint(Ws[ks+tig][nb+grp]);
        bf[nt][1]=__float_as_uint(Ws[ks+tig+4][nb+grp]);
      }
#pragma unroll
      for(int mt=0;mt<2;mt++)
#pragma unroll
        for(int nt=0;nt<6;nt++) mma8(acc[mt][nt], af[mt], bf[nt]);
    }
  }
#pragma unroll
  for(int mt=0;mt<2;mt++)
#pragma unroll
    for(int half=0;half<2;half++){
      int row=m0+wm*32+mt*16+grp+half*8;
#pragma unroll
      for(int nt=0;nt<6;nt++){
        int col=wn*48+nt*8+tig*2;
        float2 v; v.x=acc[mt][nt][half*2]; v.y=acc[mt][nt][half*2+1];
        *(float2*)(Yp+(size_t)row*NHW+col)=v;
      }
    }
}

// ---------------- final: out = gamma*(Wv @ y + bv) + x, tf32 ---------------
__global__ __launch_bounds__(256) void gemm_final(
  const float* __restrict__ Wv, const float* __restrict__ bv,
  const float* __restrict__ gamma, const float* __restrict__ x,
  float* __restrict__ out)
{
  __shared__ float Ah[16][136], Bh[16][136];
  const int bI=blockIdx.z, m0=blockIdx.y*128, n0=blockIdx.x*128;
  const float* Bp = g_y + (size_t)bI*NC*NHW;
  const int t=threadIdx.x, lane=t&31, grp=lane>>2, tig=lane&3;
  const int warp=t>>5, wm=warp>>2, wn=warp&3;

  float acc[4][4][4];
#pragma unroll
  for(int i=0;i<4;i++)for(int j=0;j<4;j++)for(int r=0;r<4;r++) acc[i][j][r]=0.f;

  const int am=t&127, ak=(t>>7)*8;
  const float* Ar = Wv + (size_t)(m0+am)*NC;
  const int bn=t&127, bk0=t>>7;

  for(int k0=0;k0<NC;k0+=16){
    float av[8];
    *(float4*)(av)   = *(const float4*)(Ar+k0+ak);
    *(float4*)(av+4) = *(const float4*)(Ar+k0+ak+4);
    float bv8[8];
#pragma unroll
    for(int i=0;i<8;i++) bv8[i]=Bp[(size_t)(k0+bk0+2*i)*NHW + n0+bn];
    if(k0) __syncthreads();
#pragma unroll
    for(int i=0;i<8;i++) Ah[ak+i][am]=tf32r(av[i]);
#pragma unroll
    for(int i=0;i<8;i++) Bh[bk0+2*i][bn]=tf32r(bv8[i]);
    __syncthreads();
#pragma unroll
    for(int ks=0;ks<16;ks+=8){
      unsigned af[4][4], bf[4][2];
#pragma unroll
      for(int mt=0;mt<4;mt++){
        int mb=wm*64+mt*16;
        af[mt][0]=__float_as_uint(Ah[ks+tig][mb+grp]);
        af[mt][1]=__float_as_uint(Ah[ks+tig][mb+grp+8]);
        af[mt][2]=__float_as_uint(Ah[ks+tig+4][mb+grp]);
        af[mt][3]=__float_as_uint(Ah[ks+tig+4][mb+grp+8]);
      }
#pragma unroll
      for(int nt=0;nt<4;nt++){
        int nb=wn*32+nt*8;
        bf[nt][0]=__float_as_uint(Bh[ks+tig][nb+grp]);
        bf[nt][1]=__float_as_uint(Bh[ks+tig+4][nb+grp]);
      }
#pragma unroll
      for(int mt=0;mt<4;mt++)
#pragma unroll
        for(int nt=0;nt<4;nt++) mma8(acc[mt][nt], af[mt], bf[nt]);
    }
  }
  const float gam=gamma[0];
#pragma unroll
  for(int mt=0;mt<4;mt++)
#pragma unroll
    for(int half=0;half<2;half++){
      int rr=m0+wm*64+mt*16+grp+half*8;
      float bias=bv[rr];
      const float* xrow = x   + ((size_t)bI*NC+rr)*NHW;
      float*       orow = out + ((size_t)bI*NC+rr)*NHW;
#pragma unroll
      for(int nt=0;nt<4;nt++){
        int cc=n0+wn*32+nt*8+tig*2;
        float2 xv=*(const float2*)(xrow+cc);
        float2 v;
        v.x=gam*(acc[mt][nt][half*2]  +bias)+xv.x;
        v.y=gam*(acc[mt][nt][half*2+1]+bias)+xv.y;
        *(float2*)(orow+cc)=v;
      }
    }
}

// ---------------- launch ----------------------------------------------------
extern "C" void kernel_launch(void* const* d_in, const int* in_sizes, int n_in,
                              void* d_out, int out_size){
  const float* x    =(const float*)d_in[0];
  const float* Wq   =(const float*)d_in[1];
  const float* bq   =(const float*)d_in[2];
  const float* Wk   =(const float*)d_in[3];
  const float* bk   =(const float*)d_in[4];
  const float* Wv   =(const float*)d_in[5];
  const float* bv   =(const float*)d_in[6];
  const float* gamma=(const float*)d_in[7];
  float* out=(float*)d_out;

  transpose96<<<NB*NC,256>>>(x,0);                 // x -> xt
  gemm_qk<<<dim3(NHW/128,NB),256>>>(x,Wq,bq,Wk,bk);
  transpose96<<<NB*NIC,256>>>(x,1);                // q -> qt
  transpose96<<<NB*NIC,256>>>(x,2);                // k -> kt
  logits_kernel<<<dim3(NB*96,2),256>>>();
  softmax_kernel<<<NB*NHW/8,256>>>();
  agg_kernel<<<dim3(4,NB*96,2),256>>>(x);
  transpose96<<<NB*NC,256>>>(x,3);                 // y += yt^T
  gemm_final<<<dim3(NHW/128,NC/128,NB),256>>>(Wv,bv,gamma,x,out);
}

// round 4
// speedup vs baseline: 1.0247x; 1.0247x over previous
#include <cuda_runtime.h>
#include <cuda_fp16.h>
#include <cstdint>
#include <cstddef>

#define NB 8
#define NC 512
#define NIC 64
#define NH 96
#define NHW 9216

// ---------------- scratch (device globals; no runtime allocation) ----------
__device__ float g_q [NB*NIC*NHW];
__device__ float g_k [NB*NIC*NHW];
__device__ float g_qt[NB*NIC*NHW];
__device__ float g_kt[NB*NIC*NHW];
__device__ float g_Ew[(size_t)NB*NHW*96];   // [b][h][w][v] row logits
__device__ float g_Eh[(size_t)NB*NHW*96];   // [b][w][h][g] col logits
__device__ __half g_Awh[(size_t)NB*NHW*96]; // softmax out (row part), fp16
__device__ __half g_Ahh[(size_t)NB*NHW*96]; // softmax out (col part, transposed layout)
__device__ __half g_xth[(size_t)NB*NC*NHW]; // x transposed, fp16
__device__ __half g_yh [(size_t)NB*NC*NHW]; // aggregation result, fp16
__device__ __half g_yth[(size_t)NB*NC*NHW]; // transposed-mode aggregation, fp16

// ---------------- helpers ---------------------------------------------------
__device__ __forceinline__ float tf32r(float v){
  unsigned u; asm("cvt.rna.tf32.f32 %0,%1;":"=r"(u):"f"(v)); return __uint_as_float(u);
}
__device__ __forceinline__ void mma8(float* d, const unsigned* a, const unsigned* b){
  asm volatile("mma.sync.aligned.m16n8k8.row.col.f32.tf32.tf32.f32 "
    "{%0,%1,%2,%3},{%4,%5,%6,%7},{%8,%9},{%0,%1,%2,%3};\n"
    :"+f"(d[0]),"+f"(d[1]),"+f"(d[2]),"+f"(d[3])
    :"r"(a[0]),"r"(a[1]),"r"(a[2]),"r"(a[3]),"r"(b[0]),"r"(b[1]));
}

// ---------------- x (fp32) -> xt (fp16) transpose ---------------------------
__global__ __launch_bounds__(256) void x2xt_f16(const float* __restrict__ x){
  __shared__ float s[96][97];
  size_t base=(size_t)blockIdx.x*NHW;
  int t=threadIdx.x;
#pragma unroll
  for(int i=0;i<36;i++){int idx=t+i*256; s[idx/96][idx%96]=x[base+idx];}
  __syncthreads();
  __half2* out=(__half2*)(g_xth+base);
#pragma unroll
  for(int i=0;i<18;i++){
    int idx=t+i*256; int r=idx/48, c2=idx%48;
    out[idx]=__floats2half2_rn(s[2*c2][r], s[2*c2+1][r]);
  }
}

// ---------------- fp32 96x96 transpose for q,k ------------------------------
__global__ __launch_bounds__(256) void transpose_qk(){
  __shared__ float s[96][97];
  const float* in  = blockIdx.y ? g_k  : g_q;
  float*       out = blockIdx.y ? g_kt : g_qt;
  size_t base=(size_t)blockIdx.x*NHW;
  int t=threadIdx.x;
#pragma unroll
  for(int i=0;i<36;i++){int idx=t+i*256; s[idx/96][idx%96]=in[base+idx];}
  __syncthreads();
#pragma unroll
  for(int i=0;i<36;i++){int idx=t+i*256; out[base+idx]=s[idx%96][idx/96];}
}

// ---------------- y += yt^T (fp16 storage, fp32 add) ------------------------
__global__ __launch_bounds__(256) void ytadd_f16(){
  __shared__ float s[96][97];
  size_t base=(size_t)blockIdx.x*NHW;
  const __half2* in=(const __half2*)(g_yth+base);
  __half2* io=(__half2*)(g_yh+base);
  int t=threadIdx.x;
#pragma unroll
  for(int i=0;i<18;i++){
    int idx=t+i*256; int r=idx/48, c2=idx%48;
    float2 v=__half22float2(in[idx]);
    s[r][2*c2]=v.x; s[r][2*c2+1]=v.y;
  }
  __syncthreads();
#pragma unroll
  for(int i=0;i<18;i++){
    int idx=t+i*256; int r=idx/48, c2=idx%48;
    float2 w=__half22float2(io[idx]);
    io[idx]=__floats2half2_rn(s[2*c2][r]+w.x, s[2*c2+1][r]+w.y);
  }
}

// ---------------- q/k projection: [Wq;Wk](128x512) @ x_b, split-tf32 -------
__global__ __launch_bounds__(256) void gemm_qk(const float* __restrict__ x,
  const float* __restrict__ Wq, const float* __restrict__ bq,
  const float* __restrict__ Wk, const float* __restrict__ bk)
{
  __shared__ float Ah[16][136], Al[16][136], Bh[16][136], Bl[16][136];
  const int bI=blockIdx.y, n0=blockIdx.x*128;
  const float* Bp = x + (size_t)bI*NC*NHW;
  const int t=threadIdx.x, lane=t&31, grp=lane>>2, tig=lane&3;
  const int warp=t>>5, wm=warp>>2, wn=warp&3;

  float acc[4][4][4];
#pragma unroll
  for(int i=0;i<4;i++)for(int j=0;j<4;j++)for(int r=0;r<4;r++) acc[i][j][r]=0.f;

  const int am=t&127, ak=(t>>7)*8;
  const float* Ar = (am<64)? Wq+(size_t)am*NC : Wk+(size_t)(am-64)*NC;
  const int bn=t&127, bk0=t>>7;

  for(int k0=0;k0<NC;k0+=16){
    float av[8];
    *(float4*)(av)   = *(const float4*)(Ar+k0+ak);
    *(float4*)(av+4) = *(const float4*)(Ar+k0+ak+4);
    float bv8[8];
#pragma unroll
    for(int i=0;i<8;i++) bv8[i]=Bp[(size_t)(k0+bk0+2*i)*NHW + n0+bn];
    if(k0) __syncthreads();
#pragma unroll
    for(int i=0;i<8;i++){float h=tf32r(av[i]); Ah[ak+i][am]=h; Al[ak+i][am]=tf32r(av[i]-h);}
#pragma unroll
    for(int i=0;i<8;i++){float h=tf32r(bv8[i]); Bh[bk0+2*i][bn]=h; Bl[bk0+2*i][bn]=tf32r(bv8[i]-h);}
    __syncthreads();
#pragma unroll
    for(int ks=0;ks<16;ks+=8){
      unsigned ah[4][4], al[4][4], bh[4][2], bl[4][2];
#pragma unroll
      for(int mt=0;mt<4;mt++){
        int mb=wm*64+mt*16;
        ah[mt][0]=__float_as_uint(Ah[ks+tig][mb+grp]);
        ah[mt][1]=__float_as_uint(Ah[ks+tig][mb+grp+8]);
        ah[mt][2]=__float_as_uint(Ah[ks+tig+4][mb+grp]);
        ah[mt][3]=__float_as_uint(Ah[ks+tig+4][mb+grp+8]);
        al[mt][0]=__float_as_uint(Al[ks+tig][mb+grp]);
        al[mt][1]=__float_as_uint(Al[ks+tig][mb+grp+8]);
        al[mt][2]=__float_as_uint(Al[ks+tig+4][mb+grp]);
        al[mt][3]=__float_as_uint(Al[ks+tig+4][mb+grp+8]);
      }
#pragma unroll
      for(int nt=0;nt<4;nt++){
        int nb=wn*32+nt*8;
        bh[nt][0]=__float_as_uint(Bh[ks+tig][nb+grp]);
        bh[nt][1]=__float_as_uint(Bh[ks+tig+4][nb+grp]);
        bl[nt][0]=__float_as_uint(Bl[ks+tig][nb+grp]);
        bl[nt][1]=__float_as_uint(Bl[ks+tig+4][nb+grp]);
      }
#pragma unroll
      for(int mt=0;mt<4;mt++)
#pragma unroll
        for(int nt=0;nt<4;nt++){
          mma8(acc[mt][nt], ah[mt], bh[nt]);
          mma8(acc[mt][nt], al[mt], bh[nt]);
          mma8(acc[mt][nt], ah[mt], bl[nt]);
        }
    }
  }
#pragma unroll
  for(int mt=0;mt<4;mt++)
#pragma unroll
    for(int half=0;half<2;half++){
      int rr=wm*64+mt*16+grp+half*8;
      float bias; float* dst;
      if(rr<64){bias=bq[rr]; dst=g_q+((size_t)bI*NIC+rr)*NHW;}
      else     {bias=bk[rr-64]; dst=g_k+((size_t)bI*NIC+(rr-64))*NHW;}
#pragma unroll
      for(int nt=0;nt<4;nt++){
        int cc=n0+wn*32+nt*8+tig*2;
        float2 v; v.x=acc[mt][nt][half*2]+bias; v.y=acc[mt][nt][half*2+1]+bias;
        *(float2*)(dst+cc)=v;
      }
    }
}

// ---------------- logits: per (b,slab) 96x96 = Q^T K over 64 ch, split-tf32
__global__ __launch_bounds__(256) void logits_kernel(){
  __shared__ float Qh[16][104], Ql[16][104], Kh[16][104], Kl[16][104];
  const int slab=blockIdx.x, mode=blockIdx.y;
  const int bI=slab/96, s=slab%96;
  const float* Qp=(mode? g_qt : g_q) + (size_t)bI*NIC*NHW + s*96;
  const float* Kp=(mode? g_kt : g_k) + (size_t)bI*NIC*NHW + s*96;
  float* Ep=(mode? g_Eh : g_Ew) + (size_t)slab*NHW;
  const int t=threadIdx.x, lane=t&31, grp=lane>>2, tig=lane&3;
  const int warp=t>>5, wm=warp>>2, wn=warp&3;   // 2 x 4 warps; tile 48 x 24

  float acc[3][3][4];
#pragma unroll
  for(int i=0;i<3;i++)for(int j=0;j<3;j++)for(int r=0;r<4;r++) acc[i][j][r]=0.f;

  for(int c0=0;c0<NIC;c0+=16){
    if(c0) __syncthreads();
#pragma unroll
    for(int i=0;i<6;i++){
      int idx=t+i*256, cl=idx/96, w=idx%96;
      float qv=Qp[(size_t)(c0+cl)*NHW + w];
      float kv=Kp[(size_t)(c0+cl)*NHW + w];
      float qh=tf32r(qv), kh=tf32r(kv);
      Qh[cl][w]=qh; Ql[cl][w]=tf32r(qv-qh);
      Kh[cl][w]=kh; Kl[cl][w]=tf32r(kv-kh);
    }
    __syncthreads();
#pragma unroll
    for(int ks=0;ks<16;ks+=8){
      unsigned ah[3][4], al[3][4], bh[3][2], bl[3][2];
#pragma unroll
      for(int mt=0;mt<3;mt++){
        int mb=wm*48+mt*16;
        ah[mt][0]=__float_as_uint(Qh[ks+tig][mb+grp]);
        ah[mt][1]=__float_as_uint(Qh[ks+tig][mb+grp+8]);
        ah[mt][2]=__float_as_uint(Qh[ks+tig+4][mb+grp]);
        ah[mt][3]=__float_as_uint(Qh[ks+tig+4][mb+grp+8]);
        al[mt][0]=__float_as_uint(Ql[ks+tig][mb+grp]);
        al[mt][1]=__float_as_uint(Ql[ks+tig][mb+grp+8]);
        al[mt][2]=__float_as_uint(Ql[ks+tig+4][mb+grp]);
        al[mt][3]=__float_as_uint(Ql[ks+tig+4][mb+grp+8]);
      }
#pragma unroll
      for(int nt=0;nt<3;nt++){
        int nb=wn*24+nt*8;
        bh[nt][0]=__float_as_uint(Kh[ks+tig][nb+grp]);
        bh[nt][1]=__float_as_uint(Kh[ks+tig+4][nb+grp]);
        bl[nt][0]=__float_as_uint(Kl[ks+tig][nb+grp]);
        bl[nt][1]=__float_as_uint(Kl[ks+tig+4][nb+grp]);
      }
#pragma unroll
      for(int mt=0;mt<3;mt++)
#pragma unroll
        for(int nt=0;nt<3;nt++){
          mma8(acc[mt][nt], ah[mt], bh[nt]);
          mma8(acc[mt][nt], al[mt], bh[nt]);
          mma8(acc[mt][nt], ah[mt], bl[nt]);
        }
    }
  }
#pragma unroll
  for(int mt=0;mt<3;mt++)
#pragma unroll
    for(int half=0;half<2;half++){
      int row=wm*48+mt*16+grp+half*8;
#pragma unroll
      for(int nt=0;nt<3;nt++){
        int col=wn*24+nt*8+tig*2;
        float2 v; v.x=acc[mt][nt][half*2]; v.y=acc[mt][nt][half*2+1];
        *(float2*)(Ep+(size_t)row*96+col)=v;
      }
    }
}

// ---------------- fused 192-wide softmax -> fp16 A, diag mask on e_h -------
__global__ __launch_bounds__(256) void softmax_kernel(){
  const int warp=threadIdx.x>>5, lane=threadIdx.x&31;
  const int p=blockIdx.x*8+warp;
  const int bI=p/NHW, rem=p%NHW, h=rem/96, w=rem%96;
  const float* ehp = g_Eh + ((size_t)(bI*96+w)*96 + h)*96;
  const float* ewp = g_Ew + (size_t)p*96;
  __half* ahp = g_Ahh + ((size_t)(bI*96+w)*96 + h)*96;
  __half* awp = g_Awh + (size_t)p*96;
  float eh[3], ew[3], m=-1e30f;
#pragma unroll
  for(int j=0;j<3;j++){
    int g=lane+32*j;
    eh[j]=(g==h)? -1e30f : ehp[g];
    ew[j]=ewp[g];
    m=fmaxf(m,fmaxf(eh[j],ew[j]));
  }
#pragma unroll
  for(int o=16;o>0;o>>=1) m=fmaxf(m,__shfl_xor_sync(0xffffffffu,m,o));
  float sum=0.f;
#pragma unroll
  for(int j=0;j<3;j++){
    eh[j]=__expf(eh[j]-m); ew[j]=__expf(ew[j]-m); sum+=eh[j]+ew[j];
  }
#pragma unroll
  for(int o=16;o>0;o>>=1) sum+=__shfl_xor_sync(0xffffffffu,sum,o);
  float inv=1.f/sum;
#pragma unroll
  for(int j=0;j<3;j++){
    int g=lane+32*j;
    ahp[g]=__float2half((g==h)?0.f:eh[j]*inv);
    awp[g]=__float2half(ew[j]*inv);
  }
}

// ---------------- aggregation: Y[c][n] = sum_k X[c][k]*A[n][k], tf32 -------
__global__ __launch_bounds__(256) void agg_f16(const float* __restrict__ x){
  __shared__ float Xs[32][136], Ws[32][104];
  const int m0=blockIdx.x*128, slab=blockIdx.y, mode=blockIdx.z;
  const int bI=slab/96, s=slab%96;
  const size_t xoff=(size_t)bI*NC*NHW + s*96;
  const float* Xpf = x + xoff;
  const __half* Xph = g_xth + xoff;
  const __half* Wt = (mode? g_Ahh : g_Awh) + (size_t)slab*NHW;  // [n][k] 96x96
  __half* Yp = (mode? g_yth : g_yh) + xoff;
  const int t=threadIdx.x, lane=t&31, grp=lane>>2, tig=lane&3;
  const int warp=t>>5, wm=warp>>1, wn=warp&1;  // 4 x 2 warps; tile 32 x 48

  float acc[2][6][4];
#pragma unroll
  for(int i=0;i<2;i++)for(int j=0;j<6;j++)for(int r=0;r<4;r++) acc[i][j][r]=0.f;

  for(int k0=0;k0<96;k0+=32){
    if(k0) __syncthreads();
    if(mode==0){
#pragma unroll
      for(int i=0;i<16;i++){
        int idx=t+i*256, kk=idx&31, c=idx>>5;
        Xs[kk][c]=tf32r(Xpf[(size_t)(m0+c)*NHW + k0+kk]);
      }
    }else{
#pragma unroll
      for(int i=0;i<16;i++){
        int idx=t+i*256, kk=idx&31, c=idx>>5;
        Xs[kk][c]=__half2float(Xph[(size_t)(m0+c)*NHW + k0+kk]);
      }
    }
#pragma unroll
    for(int i=0;i<12;i++){
      int idx=t+i*256, kk=idx&31, n=idx>>5;
      Ws[kk][n]=__half2float(Wt[(size_t)n*96 + k0+kk]);
    }
    __syncthreads();
#pragma unroll
    for(int ks=0;ks<32;ks+=8){
      unsigned af[2][4], bf[6][2];
#pragma unroll
      for(int mt=0;mt<2;mt++){
        int mb=wm*32+mt*16;
        af[mt][0]=__float_as_uint(Xs[ks+tig][mb+grp]);
        af[mt][1]=__float_as_uint(Xs[ks+tig][mb+grp+8]);
        af[mt][2]=__float_as_uint(Xs[ks+tig+4][mb+grp]);
        af[mt][3]=__float_as_uint(Xs[ks+tig+4][mb+grp+8]);
      }
#pragma unroll
      for(int nt=0;nt<6;nt++){
        int nb=wn*48+nt*8;
        bf[nt][0]=__float_as_uint(Ws[ks+tig][nb+grp]);
        bf[nt][1]=__float_as_uint(Ws[ks+tig+4][nb+grp]);
      }
#pragma unroll
      for(int mt=0;mt<2;mt++)
#pragma unroll
        for(int nt=0;nt<6;nt++) mma8(acc[mt][nt], af[mt], bf[nt]);
    }
  }
#pragma unroll
  for(int mt=0;mt<2;mt++)
#pragma unroll
    for(int half=0;half<2;half++){
      int row=m0+wm*32+mt*16+grp+half*8;
#pragma unroll
      for(int nt=0;nt<6;nt++){
        int col=wn*48+nt*8+tig*2;
        *(__half2*)(Yp+(size_t)row*NHW+col)=
            __floats2half2_rn(acc[mt][nt][half*2],acc[mt][nt][half*2+1]);
      }
    }
}

// ---------------- final: out = gamma*(Wv @ y + bv) + x, tf32 ---------------
__global__ __launch_bounds__(256) void gemm_final(
  const float* __restrict__ Wv, const float* __restrict__ bv,
  const float* __restrict__ gamma, const float* __restrict__ x,
  float* __restrict__ out)
{
  __shared__ float Ah[16][136], Bh[16][136];
  const int bI=blockIdx.z, m0=blockIdx.y*128, n0=blockIdx.x*128;
  const __half* Bp = g_yh + (size_t)bI*NC*NHW;
  const int t=threadIdx.x, lane=t&31, grp=lane>>2, tig=lane&3;
  const int warp=t>>5, wm=warp>>2, wn=warp&3;

  float acc[4][4][4];
#pragma unroll
  for(int i=0;i<4;i++)for(int j=0;j<4;j++)for(int r=0;r<4;r++) acc[i][j][r]=0.f;

  const int am=t&127, ak=(t>>7)*8;
  const float* Ar = Wv + (size_t)(m0+am)*NC;
  const int bn=t&127, bk0=t>>7;

  for(int k0=0;k0<NC;k0+=16){
    float av[8];
    *(float4*)(av)   = *(const float4*)(Ar+k0+ak);
    *(float4*)(av+4) = *(const float4*)(Ar+k0+ak+4);
    float bv8[8];
#pragma unroll
    for(int i=0;i<8;i++) bv8[i]=__half2float(Bp[(size_t)(k0+bk0+2*i)*NHW + n0+bn]);
    if(k0) __syncthreads();
#pragma unroll
    for(int i=0;i<8;i++) Ah[ak+i][am]=tf32r(av[i]);
#pragma unroll
    for(int i=0;i<8;i++) Bh[bk0+2*i][bn]=bv8[i];
    __syncthreads();
#pragma unroll
    for(int ks=0;ks<16;ks+=8){
      unsigned af[4][4], bf[4][2];
#pragma unroll
      for(int mt=0;mt<4;mt++){
        int mb=wm*64+mt*16;
        af[mt][0]=__float_as_uint(Ah[ks+tig][mb+grp]);
        af[mt][1]=__float_as_uint(Ah[ks+tig][mb+grp+8]);
        af[mt][2]=__float_as_uint(Ah[ks+tig+4][mb+grp]);
        af[mt][3]=__float_as_uint(Ah[ks+tig+4][mb+grp+8]);
      }
#pragma unroll
      for(int nt=0;nt<4;nt++){
        int nb=wn*32+nt*8;
        bf[nt][0]=__float_as_uint(Bh[ks+tig][nb+grp]);
        bf[nt][1]=__float_as_uint(Bh[ks+tig+4][nb+grp]);
      }
#pragma unroll
      for(int mt=0;mt<4;mt++)
#pragma unroll
        for(int nt=0;nt<4;nt++) mma8(acc[mt][nt], af[mt], bf[nt]);
    }
  }
  const float gam=gamma[0];
#pragma unroll
  for(int mt=0;mt<4;mt++)
#pragma unroll
    for(int half=0;half<2;half++){
      int rr=m0+wm*64+mt*16+grp+half*8;
      float bias=bv[rr];
      const float* xrow = x   + ((size_t)bI*NC+rr)*NHW;
      float*       orow = out + ((size_t)bI*NC+rr)*NHW;
#pragma unroll
      for(int nt=0;nt<4;nt++){
        int cc=n0+wn*32+nt*8+tig*2;
        float2 xv=*(const float2*)(xrow+cc);
        float2 v;
        v.x=gam*(acc[mt][nt][half*2]  +bias)+xv.x;
        v.y=gam*(acc[mt][nt][half*2+1]+bias)+xv.y;
        *(float2*)(orow+cc)=v;
      }
    }
}

// ---------------- launch ----------------------------------------------------
extern "C" void kernel_launch(void* const* d_in, const int* in_sizes, int n_in,
                              void* d_out, int out_size){
  const float* x    =(const float*)d_in[0];
  const float* Wq   =(const float*)d_in[1];
  const float* bq   =(const float*)d_in[2];
  const float* Wk   =(const float*)d_in[3];
  const float* bk   =(const float*)d_in[4];
  const float* Wv   =(const float*)d_in[5];
  const float* bv   =(const float*)d_in[6];
  const float* gamma=(const float*)d_in[7];
  float* out=(float*)d_out;

  x2xt_f16<<<NB*NC,256>>>(x);
  gemm_qk<<<dim3(NHW/128,NB),256>>>(x,Wq,bq,Wk,bk);
  transpose_qk<<<dim3(NB*NIC,2),256>>>();
  logits_kernel<<<dim3(NB*96,2),256>>>();
  softmax_kernel<<<NB*NHW/8,256>>>();
  agg_f16<<<dim3(4,NB*96,2),256>>>(x);
  ytadd_f16<<<NB*NC,256>>>();
  gemm_final<<<dim3(NHW/128,NC/128,NB),256>>>(Wv,bv,gamma,x,out);
}

// round 6
// speedup vs baseline: 1.4718x; 1.4363x over previous
#include <cuda_runtime.h>
#include <cuda_fp16.h>
#include <cstdint>
#include <cstddef>

#define NB 8
#define NC 512
#define NIC 64
#define NH 96
#define NHW 9216

// ---------------- scratch (device globals; no runtime allocation) ----------
__device__ float g_q [NB*NIC*NHW];
__device__ float g_k [NB*NIC*NHW];
__device__ float g_qt[NB*NIC*NHW];
__device__ float g_kt[NB*NIC*NHW];
__device__ float g_Ew[(size_t)NB*NHW*96];   // [b][h][w][v] row logits
__device__ float g_Eh[(size_t)NB*NHW*96];   // [b][w][h][g] col logits
__device__ __half g_Awh[(size_t)NB*NHW*96]; // softmax out (row part), fp16
__device__ __half g_Ahh[(size_t)NB*NHW*96]; // softmax out (col part, transposed layout)
__device__ __half g_xth[(size_t)NB*NC*NHW]; // x transposed, fp16
__device__ __half g_yh [(size_t)NB*NC*NHW]; // aggregation result, fp16
__device__ __half g_yth[(size_t)NB*NC*NHW]; // transposed-mode aggregation, fp16

// ---------------- helpers ---------------------------------------------------
__device__ __forceinline__ void mma16h(float* d, const unsigned* a, const unsigned* b){
  asm volatile("mma.sync.aligned.m16n8k16.row.col.f32.f16.f16.f32 "
    "{%0,%1,%2,%3},{%4,%5,%6,%7},{%8,%9},{%0,%1,%2,%3};\n"
    :"+f"(d[0]),"+f"(d[1]),"+f"(d[2]),"+f"(d[3])
    :"r"(a[0]),"r"(a[1]),"r"(a[2]),"r"(a[3]),"r"(b[0]),"r"(b[1]));
}
__device__ __forceinline__ unsigned packh2(float a, float b){
  __half2 v=__floats2half2_rn(a,b); return *reinterpret_cast<unsigned*>(&v);
}
// split v into fp16 hi + fp16 lo (hi+lo ~ 21-bit mantissa of v)
__device__ __forceinline__ void split2(float v0, float v1, unsigned& hi, unsigned& lo){
  __half h0=__float2half_rn(v0), h1=__float2half_rn(v1);
  float  r0=v0-__half2float(h0), r1=v1-__half2float(h1);
  __half2 hv=__halves2half2(h0,h1);
  __half2 lv=__floats2half2_rn(r0,r1);
  hi=*reinterpret_cast<unsigned*>(&hv);
  lo=*reinterpret_cast<unsigned*>(&lv);
}

// ---------------- x (fp32) -> xt (fp16) transpose ---------------------------
__global__ __launch_bounds__(256) void x2xt_f16(const float* __restrict__ x){
  __shared__ float s[96][97];
  size_t base=(size_t)blockIdx.x*NHW;
  int t=threadIdx.x;
#pragma unroll
  for(int i=0;i<36;i++){int idx=t+i*256; s[idx/96][idx%96]=x[base+idx];}
  __syncthreads();
  __half2* out=(__half2*)(g_xth+base);
#pragma unroll
  for(int i=0;i<18;i++){
    int idx=t+i*256; int r=idx/48, c2=idx%48;
    out[idx]=__floats2half2_rn(s[2*c2][r], s[2*c2+1][r]);
  }
}

// ---------------- fp32 96x96 transpose for q,k ------------------------------
__global__ __launch_bounds__(256) void transpose_qk(){
  __shared__ float s[96][97];
  const float* in  = blockIdx.y ? g_k  : g_q;
  float*       out = blockIdx.y ? g_kt : g_qt;
  size_t base=(size_t)blockIdx.x*NHW;
  int t=threadIdx.x;
#pragma unroll
  for(int i=0;i<36;i++){int idx=t+i*256; s[idx/96][idx%96]=in[base+idx];}
  __syncthreads();
#pragma unroll
  for(int i=0;i<36;i++){int idx=t+i*256; out[base+idx]=s[idx%96][idx/96];}
}

// ---------------- y += yt^T (fp16 storage, fp32 add) ------------------------
__global__ __launch_bounds__(256) void ytadd_f16(){
  __shared__ float s[96][97];
  size_t base=(size_t)blockIdx.x*NHW;
  const __half2* in=(const __half2*)(g_yth+base);
  __half2* io=(__half2*)(g_yh+base);
  int t=threadIdx.x;
#pragma unroll
  for(int i=0;i<18;i++){
    int idx=t+i*256; int r=idx/48, c2=idx%48;
    float2 v=__half22float2(in[idx]);
    s[r][2*c2]=v.x; s[r][2*c2+1]=v.y;
  }
  __syncthreads();
#pragma unroll
  for(int i=0;i<18;i++){
    int idx=t+i*256; int r=idx/48, c2=idx%48;
    float2 w=__half22float2(io[idx]);
    io[idx]=__floats2half2_rn(s[2*c2][r]+w.x, s[2*c2+1][r]+w.y);
  }
}

// ---------------- q/k projection: [Wq;Wk](128x512) @ x_b, split-fp16 -------
__global__ __launch_bounds__(256) void gemm_qk(const float* __restrict__ x,
  const float* __restrict__ Wq, const float* __restrict__ bq,
  const float* __restrict__ Wk, const float* __restrict__ bk)
{
  __shared__ unsigned Ahs[16][136], Als[16][136], Bhs[16][136], Bls[16][136];
  const int bI=blockIdx.y, n0=blockIdx.x*128;
  const float* Bp = x + (size_t)bI*NC*NHW;
  const int t=threadIdx.x, lane=t&31, grp=lane>>2, tig=lane&3;
  const int warp=t>>5, wm=warp>>2, wn=warp&3;

  float acc[4][4][4];
#pragma unroll
  for(int i=0;i<4;i++)for(int j=0;j<4;j++)for(int r=0;r<4;r++) acc[i][j][r]=0.f;

  const int am=t&127, aks=(t>>7)*16;     // 16 consecutive k per thread
  const float* Ar = (am<64)? Wq+(size_t)am*NC : Wk+(size_t)(am-64)*NC;
  const int bn=t&127, bkp=(t>>7)*8;      // 8 k-pairs per thread

  for(int k0=0;k0<NC;k0+=32){
    float av[16];
#pragma unroll
    for(int i=0;i<4;i++) *(float4*)(av+4*i)=*(const float4*)(Ar+k0+aks+4*i);
    float bv0[8], bv1[8];
#pragma unroll
    for(int j=0;j<8;j++){
      int row=k0+2*(bkp+j);
      bv0[j]=Bp[(size_t)row*NHW+n0+bn];
      bv1[j]=Bp[(size_t)(row+1)*NHW+n0+bn];
    }
    if(k0) __syncthreads();
#pragma unroll
    for(int j=0;j<8;j++){
      unsigned hi,lo; split2(av[2*j],av[2*j+1],hi,lo);
      Ahs[aks/2+j][am]=hi; Als[aks/2+j][am]=lo;
    }
#pragma unroll
    for(int j=0;j<8;j++){
      unsigned hi,lo; split2(bv0[j],bv1[j],hi,lo);
      Bhs[bkp+j][bn]=hi; Bls[bkp+j][bn]=lo;
    }
    __syncthreads();
#pragma unroll
    for(int s=0;s<2;s++){
      const int pb=s*8;
      unsigned ah[4][4], al[4][4], bh[4][2], bl[4][2];
#pragma unroll
      for(int mt=0;mt<4;mt++){
        int mb=wm*64+mt*16;
        ah[mt][0]=Ahs[pb+tig][mb+grp];   ah[mt][1]=Ahs[pb+tig][mb+grp+8];
        ah[mt][2]=Ahs[pb+tig+4][mb+grp]; ah[mt][3]=Ahs[pb+tig+4][mb+grp+8];
        al[mt][0]=Als[pb+tig][mb+grp];   al[mt][1]=Als[pb+tig][mb+grp+8];
        al[mt][2]=Als[pb+tig+4][mb+grp]; al[mt][3]=Als[pb+tig+4][mb+grp+8];
      }
#pragma unroll
      for(int nt=0;nt<4;nt++){
        int nb=wn*32+nt*8;
        bh[nt][0]=Bhs[pb+tig][nb+grp]; bh[nt][1]=Bhs[pb+tig+4][nb+grp];
        bl[nt][0]=Bls[pb+tig][nb+grp]; bl[nt][1]=Bls[pb+tig+4][nb+grp];
      }
#pragma unroll
      for(int mt=0;mt<4;mt++)
#pragma unroll
        for(int nt=0;nt<4;nt++){
          mma16h(acc[mt][nt], ah[mt], bh[nt]);
          mma16h(acc[mt][nt], al[mt], bh[nt]);
          mma16h(acc[mt][nt], ah[mt], bl[nt]);
        }
    }
  }
#pragma unroll
  for(int mt=0;mt<4;mt++)
#pragma unroll
    for(int half=0;half<2;half++){
      int rr=wm*64+mt*16+grp+half*8;
      float bias; float* dst;
      if(rr<64){bias=bq[rr]; dst=g_q+((size_t)bI*NIC+rr)*NHW;}
      else     {bias=bk[rr-64]; dst=g_k+((size_t)bI*NIC+(rr-64))*NHW;}
#pragma unroll
      for(int nt=0;nt<4;nt++){
        int cc=n0+wn*32+nt*8+tig*2;
        float2 v; v.x=acc[mt][nt][half*2]+bias; v.y=acc[mt][nt][half*2+1]+bias;
        *(float2*)(dst+cc)=v;
      }
    }
}

// ---------------- logits: per (b,slab) 96x96 = Q^T K over 64 ch, split-fp16
__global__ __launch_bounds__(256) void logits_kernel(){
  __shared__ unsigned Qh[16][104], Ql[16][104], Kh[16][104], Kl[16][104];
  const int slab=blockIdx.x, mode=blockIdx.y;
  const int bI=slab/96, s=slab%96;
  const float* Qp=(mode? g_qt : g_q) + (size_t)bI*NIC*NHW + s*96;
  const float* Kp=(mode? g_kt : g_k) + (size_t)bI*NIC*NHW + s*96;
  float* Ep=(mode? g_Eh : g_Ew) + (size_t)slab*NHW;
  const int t=threadIdx.x, lane=t&31, grp=lane>>2, tig=lane&3;
  const int warp=t>>5, wm=warp>>2, wn=warp&3;   // 2 x 4 warps; tile 48 x 24

  float acc[3][3][4];
#pragma unroll
  for(int i=0;i<3;i++)for(int j=0;j<3;j++)for(int r=0;r<4;r++) acc[i][j][r]=0.f;

  for(int c0=0;c0<NIC;c0+=32){
    if(c0) __syncthreads();
#pragma unroll
    for(int i=0;i<6;i++){
      int idx=t+i*256, p=idx/96, w=idx%96;
      int ch=c0+2*p;
      float q0=Qp[(size_t)ch*NHW+w],     q1=Qp[(size_t)(ch+1)*NHW+w];
      float k0v=Kp[(size_t)ch*NHW+w],    k1v=Kp[(size_t)(ch+1)*NHW+w];
      unsigned hi,lo;
      split2(q0,q1,hi,lo); Qh[p][w]=hi; Ql[p][w]=lo;
      split2(k0v,k1v,hi,lo); Kh[p][w]=hi; Kl[p][w]=lo;
    }
    __syncthreads();
#pragma unroll
    for(int s2=0;s2<2;s2++){
      const int pb=s2*8;
      unsigned ah[3][4], al[3][4], bh[3][2], bl[3][2];
#pragma unroll
      for(int mt=0;mt<3;mt++){
        int mb=wm*48+mt*16;
        ah[mt][0]=Qh[pb+tig][mb+grp];   ah[mt][1]=Qh[pb+tig][mb+grp+8];
        ah[mt][2]=Qh[pb+tig+4][mb+grp]; ah[mt][3]=Qh[pb+tig+4][mb+grp+8];
        al[mt][0]=Ql[pb+tig][mb+grp];   al[mt][1]=Ql[pb+tig][mb+grp+8];
        al[mt][2]=Ql[pb+tig+4][mb+grp]; al[mt][3]=Ql[pb+tig+4][mb+grp+8];
      }
#pragma unroll
      for(int nt=0;nt<3;nt++){
        int nb=wn*24+nt*8;
        bh[nt][0]=Kh[pb+tig][nb+grp]; bh[nt][1]=Kh[pb+tig+4][nb+grp];
        bl[nt][0]=Kl[pb+tig][nb+grp]; bl[nt][1]=Kl[pb+tig+4][nb+grp];
      }
#pragma unroll
      for(int mt=0;mt<3;mt++)
#pragma unroll
        for(int nt=0;nt<3;nt++){
          mma16h(acc[mt][nt], ah[mt], bh[nt]);
          mma16h(acc[mt][nt], al[mt], bh[nt]);
          mma16h(acc[mt][nt], ah[mt], bl[nt]);
        }
    }
  }
#pragma unroll
  for(int mt=0;mt<3;mt++)
#pragma unroll
    for(int half=0;half<2;half++){
      int row=wm*48+mt*16+grp+half*8;
#pragma unroll
      for(int nt=0;nt<3;nt++){
        int col=wn*24+nt*8+tig*2;
        float2 v; v.x=acc[mt][nt][half*2]; v.y=acc[mt][nt][half*2+1];
        *(float2*)(Ep+(size_t)row*96+col)=v;
      }
    }
}

// ---------------- fused 192-wide softmax -> fp16 A, diag mask on e_h -------
__global__ __launch_bounds__(256) void softmax_kernel(){
  const int warp=threadIdx.x>>5, lane=threadIdx.x&31;
  const int p=blockIdx.x*8+warp;
  const int bI=p/NHW, rem=p%NHW, h=rem/96, w=rem%96;
  const float* ehp = g_Eh + ((size_t)(bI*96+w)*96 + h)*96;
  const float* ewp = g_Ew + (size_t)p*96;
  __half* ahp = g_Ahh + ((size_t)(bI*96+w)*96 + h)*96;
  __half* awp = g_Awh + (size_t)p*96;
  float eh[3], ew[3], m=-1e30f;
#pragma unroll
  for(int j=0;j<3;j++){
    int g=lane+32*j;
    eh[j]=(g==h)? -1e30f : ehp[g];
    ew[j]=ewp[g];
    m=fmaxf(m,fmaxf(eh[j],ew[j]));
  }
#pragma unroll
  for(int o=16;o>0;o>>=1) m=fmaxf(m,__shfl_xor_sync(0xffffffffu,m,o));
  float sum=0.f;
#pragma unroll
  for(int j=0;j<3;j++){
    eh[j]=__expf(eh[j]-m); ew[j]=__expf(ew[j]-m); sum+=eh[j]+ew[j];
  }
#pragma unroll
  for(int o=16;o>0;o>>=1) sum+=__shfl_xor_sync(0xffffffffu,sum,o);
  float inv=1.f/sum;
#pragma unroll
  for(int j=0;j<3;j++){
    int g=lane+32*j;
    ahp[g]=__float2half((g==h)?0.f:eh[j]*inv);
    awp[g]=__float2half(ew[j]*inv);
  }
}

// ---------------- aggregation (fp16 mma): Y[c][n] = sum_k X[c][k]*A[n][k] --
__global__ __launch_bounds__(256) void agg_f16(const float* __restrict__ x){
  __shared__ unsigned Xs[48][136];
  __shared__ unsigned Ws[48][104];
  const int m0=blockIdx.x*128, slab=blockIdx.y, mode=blockIdx.z;
  const int bI=slab/96, s=slab%96;
  const size_t xoff=(size_t)bI*NC*NHW + s*96;
  const float* Xpf = x + xoff;
  const __half* Xph = g_xth + xoff;
  const __half* Wt = (mode? g_Ahh : g_Awh) + (size_t)slab*NHW;  // [n][k] 96x96
  __half* Yp = (mode? g_yth : g_yh) + xoff;
  const int t=threadIdx.x, lane=t&31, grp=lane>>2, tig=lane&3;
  const int warp=t>>5, wm=warp>>1, wn=warp&1;  // 4 x 2 warps; tile 32 x 48

  float acc[2][6][4];
#pragma unroll
  for(int i=0;i<2;i++)for(int j=0;j<6;j++)for(int r=0;r<4;r++) acc[i][j][r]=0.f;

  if(mode==0){
#pragma unroll
    for(int i=0;i<24;i++){
      int idx=t+i*256; int c=idx/48, pp=idx%48;
      float2 f=*(const float2*)(Xpf+(size_t)(m0+c)*NHW+2*pp);
      Xs[pp][c]=packh2(f.x,f.y);
    }
  }else{
#pragma unroll
    for(int i=0;i<24;i++){
      int idx=t+i*256; int c=idx/48, pp=idx%48;
      Xs[pp][c]=*(const unsigned*)(Xph+(size_t)(m0+c)*NHW+2*pp);
    }
  }
#pragma unroll
  for(int i=0;i<18;i++){
    int idx=t+i*256; int n=idx/48, pp=idx%48;
    Ws[pp][n]=*(const unsigned*)(Wt+(size_t)n*96+2*pp);
  }
  __syncthreads();

#pragma unroll
  for(int kk=0;kk<6;kk++){
    const int pb=kk*8;
    unsigned a[2][4], b[6][2];
#pragma unroll
    for(int mt=0;mt<2;mt++){
      int mb=wm*32+mt*16;
      a[mt][0]=Xs[pb+tig][mb+grp];   a[mt][1]=Xs[pb+tig][mb+grp+8];
      a[mt][2]=Xs[pb+tig+4][mb+grp]; a[mt][3]=Xs[pb+tig+4][mb+grp+8];
    }
#pragma unroll
    for(int nt=0;nt<6;nt++){
      int nb=wn*48+nt*8;
      b[nt][0]=Ws[pb+tig][nb+grp]; b[nt][1]=Ws[pb+tig+4][nb+grp];
    }
#pragma unroll
    for(int mt=0;mt<2;mt++)
#pragma unroll
      for(int nt=0;nt<6;nt++) mma16h(acc[mt][nt], a[mt], b[nt]);
  }

#pragma unroll
  for(int mt=0;mt<2;mt++)
#pragma unroll
    for(int half=0;half<2;half++){
      int row=m0+wm*32+mt*16+grp+half*8;
#pragma unroll
      for(int nt=0;nt<6;nt++){
        int col=wn*48+nt*8+tig*2;
        *(__half2*)(Yp+(size_t)row*NHW+col)=
            __floats2half2_rn(acc[mt][nt][half*2],acc[mt][nt][half*2+1]);
      }
    }
}

// ---------------- final (fp16 mma): out = gamma*(Wv @ y + bv) + x ----------
__global__ __launch_bounds__(256) void final_f16(
  const float* __restrict__ Wv, const float* __restrict__ bv,
  const float* __restrict__ gamma, const float* __restrict__ x,
  float* __restrict__ out)
{
  __shared__ unsigned As[32][136], Bs[32][136];
  const int bI=blockIdx.z, m0=blockIdx.y*128, n0=blockIdx.x*128;
  const __half* Bp = g_yh + (size_t)bI*NC*NHW;
  const int t=threadIdx.x, lane=t&31, grp=lane>>2, tig=lane&3;
  const int warp=t>>5, wm=warp>>2, wn=warp&3;

  float acc[4][4][4];
#pragma unroll
  for(int i=0;i<4;i++)for(int j=0;j<4;j++)for(int r=0;r<4;r++) acc[i][j][r]=0.f;

  for(int k0=0;k0<NC;k0+=64){
    if(k0) __syncthreads();
    // A: 128 m x 32 k-pairs
#pragma unroll
    for(int i=0;i<16;i++){
      int idx=t+i*256; int m=idx/32, pp=idx%32;
      float2 f=*(const float2*)(Wv+(size_t)(m0+m)*NC+k0+2*pp);
      As[pp][m]=packh2(f.x,f.y);
    }
    // B: build k-pairs from two consecutive y rows
#pragma unroll
    for(int i=0;i<8;i++){
      int idx=t+i*256; int np=idx&63, k2=idx>>6;
      unsigned r0=*(const unsigned*)(Bp+(size_t)(k0+2*k2  )*NHW+n0+2*np);
      unsigned r1=*(const unsigned*)(Bp+(size_t)(k0+2*k2+1)*NHW+n0+2*np);
      Bs[k2][2*np  ]=(r0&0xffffu)|(r1<<16);
      Bs[k2][2*np+1]=(r0>>16)|(r1&0xffff0000u);
    }
    __syncthreads();
#pragma unroll
    for(int kk=0;kk<4;kk++){
      const int pb=kk*8;
      unsigned a[4][4], b[4][2];
#pragma unroll
      for(int mt=0;mt<4;mt++){
        int mb=wm*64+mt*16;
        a[mt][0]=As[pb+tig][mb+grp];   a[mt][1]=As[pb+tig][mb+grp+8];
        a[mt][2]=As[pb+tig+4][mb+grp]; a[mt][3]=As[pb+tig+4][mb+grp+8];
      }
#pragma unroll
      for(int nt=0;nt<4;nt++){
        int nb=wn*32+nt*8;
        b[nt][0]=Bs[pb+tig][nb+grp]; b[nt][1]=Bs[pb+tig+4][nb+grp];
      }
#pragma unroll
      for(int mt=0;mt<4;mt++)
#pragma unroll
        for(int nt=0;nt<4;nt++) mma16h(acc[mt][nt], a[mt], b[nt]);
    }
  }
  const float gam=gamma[0];
#pragma unroll
  for(int mt=0;mt<4;mt++)
#pragma unroll
    for(int half=0;half<2;half++){
      int rr=m0+wm*64+mt*16+grp+half*8;
      float bias=bv[rr];
      const float* xrow = x   + ((size_t)bI*NC+rr)*NHW;
      float*       orow = out + ((size_t)bI*NC+rr)*NHW;
#pragma unroll
      for(int nt=0;nt<4;nt++){
        int cc=n0+wn*32+nt*8+tig*2;
        float2 xv=*(const float2*)(xrow+cc);
        float2 v;
        v.x=gam*(acc[mt][nt][half*2]  +bias)+xv.x;
        v.y=gam*(acc[mt][nt][half*2+1]+bias)+xv.y;
        *(float2*)(orow+cc)=v;
      }
    }
}

// ---------------- launch ----------------------------------------------------
extern "C" void kernel_launch(void* const* d_in, const int* in_sizes, int n_in,
                              void* d_out, int out_size){
  const float* x    =(const float*)d_in[0];
  const float* Wq   =(const float*)d_in[1];
  const float* bq   =(const float*)d_in[2];
  const float* Wk   =(const float*)d_in[3];
  const float* bk   =(const float*)d_in[4];
  const float* Wv   =(const float*)d_in[5];
  const float* bv   =(const float*)d_in[6];
  const float* gamma=(const float*)d_in[7];
  float* out=(float*)d_out;

  x2xt_f16<<<NB*NC,256>>>(x);
  gemm_qk<<<dim3(NHW/128,NB),256>>>(x,Wq,bq,Wk,bk);
  transpose_qk<<<dim3(NB*NIC,2),256>>>();
  logits_kernel<<<dim3(NB*96,2),256>>>();
  softmax_kernel<<<NB*NHW/8,256>>>();
  agg_f16<<<dim3(4,NB*96,2),256>>>(x);
  ytadd_f16<<<NB*NC,256>>>();
  final_f16<<<dim3(NHW/128,NC/128,NB),256>>>(Wv,bv,gamma,x,out);
}

// round 7
// speedup vs baseline: 1.5774x; 1.0717x over previous
#include <cuda_runtime.h>
#include <cuda_fp16.h>
#include <cstdint>
#include <cstddef>

#define NB 8
#define NC 512
#define NIC 64
#define NHW 9216

// ---------------- scratch (device globals; no runtime allocation) ----------
__device__ float g_q [NB*NIC*NHW];
__device__ float g_k [NB*NIC*NHW];
__device__ float g_qt[NB*NIC*NHW];
__device__ float g_kt[NB*NIC*NHW];
__device__ float g_Ew[(size_t)NB*NHW*96];      // [b][h][w][v] row logits
__device__ float g_Eh[(size_t)NB*NHW*96];      // [b][w][h][g] col logits
__device__ __half g_Awh[(size_t)NB*NHW*96];    // softmax row part [b][h][w][v]
__device__ __half g_Ahh[(size_t)NB*NHW*96];    // softmax col part [b][w][h][g]
__device__ __half g_v2 [(size_t)NB*NHW*NC];    // v = Wv@x, channel-minor [b][h][w][c]
__device__ __half g_o2w[(size_t)NB*NHW*NC];    // row-agg out [b][h][w][c]
__device__ __half g_o2h[(size_t)NB*NHW*NC];    // col-agg out [b][w][h][c]

// ---------------- helpers ---------------------------------------------------
__device__ __forceinline__ void mma16h(float* d, const unsigned* a, const unsigned* b){
  asm volatile("mma.sync.aligned.m16n8k16.row.col.f32.f16.f16.f32 "
    "{%0,%1,%2,%3},{%4,%5,%6,%7},{%8,%9},{%0,%1,%2,%3};\n"
    :"+f"(d[0]),"+f"(d[1]),"+f"(d[2]),"+f"(d[3])
    :"r"(a[0]),"r"(a[1]),"r"(a[2]),"r"(a[3]),"r"(b[0]),"r"(b[1]));
}
__device__ __forceinline__ unsigned packh2(float a, float b){
  __half2 v=__floats2half2_rn(a,b); return *reinterpret_cast<unsigned*>(&v);
}
__device__ __forceinline__ void split2(float v0, float v1, unsigned& hi, unsigned& lo){
  __half h0=__float2half_rn(v0), h1=__float2half_rn(v1);
  float  r0=v0-__half2float(h0), r1=v1-__half2float(h1);
  __half2 hv=__halves2half2(h0,h1);
  __half2 lv=__floats2half2_rn(r0,r1);
  hi=*reinterpret_cast<unsigned*>(&hv);
  lo=*reinterpret_cast<unsigned*>(&lv);
}

// ---------------- fused projection: [Wq;Wk] split-fp16 + Wv plain fp16 -----
// grid (72 n-chunks, 5 m-parts, NB).  m-part 0: q/k (split, fp32 out).
// m-parts 1..4: 128 Wv rows each, plain fp16, epilogue transposes tile to
// channel-minor v2[b][pix][c] via smem.
__global__ __launch_bounds__(256) void gemm_qkv(
  const float* __restrict__ x,
  const float* __restrict__ Wq, const float* __restrict__ bq,
  const float* __restrict__ Wk, const float* __restrict__ bk,
  const float* __restrict__ Wv)
{
  __shared__ __align__(16) unsigned sbuf[4*16*136];
  unsigned (*Ahs)[136] = (unsigned(*)[136])(sbuf);
  unsigned (*Als)[136] = (unsigned(*)[136])(sbuf+2176);
  unsigned (*Bhs)[136] = (unsigned(*)[136])(sbuf+4352);
  unsigned (*Bls)[136] = (unsigned(*)[136])(sbuf+6528);

  const int bI=blockIdx.z, n0=blockIdx.x*128, mpart=blockIdx.y;
  const float* Bp = x + (size_t)bI*NC*NHW;
  const int t=threadIdx.x, lane=t&31, grp=lane>>2, tig=lane&3;
  const int warp=t>>5, wm=warp>>2, wn=warp&3;

  float acc[4][4][4];
#pragma unroll
  for(int i=0;i<4;i++)for(int j=0;j<4;j++)for(int r=0;r<4;r++) acc[i][j][r]=0.f;

  const int am=t&127, aks=(t>>7)*16;
  const int bn=t&127, bkp=(t>>7)*8;

  if(mpart==0){
    // ---- q/k path: split-fp16 (proven R6 code) ----
    const float* Ar = (am<64)? Wq+(size_t)am*NC : Wk+(size_t)(am-64)*NC;
    for(int k0=0;k0<NC;k0+=32){
      float av[16];
#pragma unroll
      for(int i=0;i<4;i++) *(float4*)(av+4*i)=*(const float4*)(Ar+k0+aks+4*i);
      float bv0[8], bv1[8];
#pragma unroll
      for(int j=0;j<8;j++){
        int row=k0+2*(bkp+j);
        bv0[j]=Bp[(size_t)row*NHW+n0+bn];
        bv1[j]=Bp[(size_t)(row+1)*NHW+n0+bn];
      }
      if(k0) __syncthreads();
#pragma unroll
      for(int j=0;j<8;j++){
        unsigned hi,lo; split2(av[2*j],av[2*j+1],hi,lo);
        Ahs[aks/2+j][am]=hi; Als[aks/2+j][am]=lo;
      }
#pragma unroll
      for(int j=0;j<8;j++){
        unsigned hi,lo; split2(bv0[j],bv1[j],hi,lo);
        Bhs[bkp+j][bn]=hi; Bls[bkp+j][bn]=lo;
      }
      __syncthreads();
#pragma unroll
      for(int s=0;s<2;s++){
        const int pb=s*8;
        unsigned ah[4][4], al[4][4], bh[4][2], bl[4][2];
#pragma unroll
        for(int mt=0;mt<4;mt++){
          int mb=wm*64+mt*16;
          ah[mt][0]=Ahs[pb+tig][mb+grp];   ah[mt][1]=Ahs[pb+tig][mb+grp+8];
          ah[mt][2]=Ahs[pb+tig+4][mb+grp]; ah[mt][3]=Ahs[pb+tig+4][mb+grp+8];
          al[mt][0]=Als[pb+tig][mb+grp];   al[mt][1]=Als[pb+tig][mb+grp+8];
          al[mt][2]=Als[pb+tig+4][mb+grp]; al[mt][3]=Als[pb+tig+4][mb+grp+8];
        }
#pragma unroll
        for(int nt=0;nt<4;nt++){
          int nb=wn*32+nt*8;
          bh[nt][0]=Bhs[pb+tig][nb+grp]; bh[nt][1]=Bhs[pb+tig+4][nb+grp];
          bl[nt][0]=Bls[pb+tig][nb+grp]; bl[nt][1]=Bls[pb+tig+4][nb+grp];
        }
#pragma unroll
        for(int mt=0;mt<4;mt++)
#pragma unroll
          for(int nt=0;nt<4;nt++){
            mma16h(acc[mt][nt], ah[mt], bh[nt]);
            mma16h(acc[mt][nt], al[mt], bh[nt]);
            mma16h(acc[mt][nt], ah[mt], bl[nt]);
          }
      }
    }
#pragma unroll
    for(int mt=0;mt<4;mt++)
#pragma unroll
      for(int half=0;half<2;half++){
        int rr=wm*64+mt*16+grp+half*8;
        float bias; float* dst;
        if(rr<64){bias=bq[rr]; dst=g_q+((size_t)bI*NIC+rr)*NHW;}
        else     {bias=bk[rr-64]; dst=g_k+((size_t)bI*NIC+(rr-64))*NHW;}
#pragma unroll
        for(int nt=0;nt<4;nt++){
          int cc=n0+wn*32+nt*8+tig*2;
          float2 v; v.x=acc[mt][nt][half*2]+bias; v.y=acc[mt][nt][half*2+1]+bias;
          *(float2*)(dst+cc)=v;
        }
      }
  } else {
    // ---- v path: plain fp16, transposed channel-minor output ----
    const int m0v=(mpart-1)*128;
    const float* Ar = Wv + (size_t)(m0v+am)*NC;
    for(int k0=0;k0<NC;k0+=32){
      float av[16];
#pragma unroll
      for(int i=0;i<4;i++) *(float4*)(av+4*i)=*(const float4*)(Ar+k0+aks+4*i);
      float bv0[8], bv1[8];
#pragma unroll
      for(int j=0;j<8;j++){
        int row=k0+2*(bkp+j);
        bv0[j]=Bp[(size_t)row*NHW+n0+bn];
        bv1[j]=Bp[(size_t)(row+1)*NHW+n0+bn];
      }
      if(k0) __syncthreads();
#pragma unroll
      for(int j=0;j<8;j++) Ahs[aks/2+j][am]=packh2(av[2*j],av[2*j+1]);
#pragma unroll
      for(int j=0;j<8;j++) Bhs[bkp+j][bn]=packh2(bv0[j],bv1[j]);
      __syncthreads();
#pragma unroll
      for(int s=0;s<2;s++){
        const int pb=s*8;
        unsigned a[4][4], b[4][2];
#pragma unroll
        for(int mt=0;mt<4;mt++){
          int mb=wm*64+mt*16;
          a[mt][0]=Ahs[pb+tig][mb+grp];   a[mt][1]=Ahs[pb+tig][mb+grp+8];
          a[mt][2]=Ahs[pb+tig+4][mb+grp]; a[mt][3]=Ahs[pb+tig+4][mb+grp+8];
        }
#pragma unroll
        for(int nt=0;nt<4;nt++){
          int nb=wn*32+nt*8;
          b[nt][0]=Bhs[pb+tig][nb+grp]; b[nt][1]=Bhs[pb+tig+4][nb+grp];
        }
#pragma unroll
        for(int mt=0;mt<4;mt++)
#pragma unroll
          for(int nt=0;nt<4;nt++) mma16h(acc[mt][nt], a[mt], b[nt]);
      }
    }
    // epilogue: transpose 128m(c) x 128n(pix) tile through smem, write v2
    __syncthreads();
    __half (*st)[136] = (__half(*)[136])sbuf;
#pragma unroll
    for(int mt=0;mt<4;mt++)
#pragma unroll
      for(int half=0;half<2;half++){
        int m=wm*64+mt*16+grp+half*8;
#pragma unroll
        for(int nt=0;nt<4;nt++){
          int n=wn*32+nt*8+tig*2;
          st[n][m]  =__float2half(acc[mt][nt][half*2]);
          st[n+1][m]=__float2half(acc[mt][nt][half*2+1]);
        }
      }
    __syncthreads();
    __half2* v2p=(__half2*)(g_v2 + ((size_t)bI*NHW + n0)*NC + m0v);
#pragma unroll
    for(int i=0;i<32;i++){
      int lin=i*256+t, p=lin>>6, cj=lin&63;
      v2p[(size_t)p*(NC/2)+cj] = *(__half2*)&st[p][2*cj];
    }
  }
}

// ---------------- fp32 96x96 transpose for q,k (unchanged) ------------------
__global__ __launch_bounds__(256) void transpose_qk(){
  __shared__ float s[96][97];
  const float* in  = blockIdx.y ? g_k  : g_q;
  float*       out = blockIdx.y ? g_kt : g_qt;
  size_t base=(size_t)blockIdx.x*NHW;
  int t=threadIdx.x;
#pragma unroll
  for(int i=0;i<36;i++){int idx=t+i*256; s[idx/96][idx%96]=in[base+idx];}
  __syncthreads();
#pragma unroll
  for(int i=0;i<36;i++){int idx=t+i*256; out[base+idx]=s[idx%96][idx/96];}
}

// ---------------- logits (unchanged from R6) --------------------------------
__global__ __launch_bounds__(256) void logits_kernel(){
  __shared__ unsigned Qh[16][104], Ql[16][104], Kh[16][104], Kl[16][104];
  const int slab=blockIdx.x, mode=blockIdx.y;
  const int bI=slab/96, s=slab%96;
  const float* Qp=(mode? g_qt : g_q) + (size_t)bI*NIC*NHW + s*96;
  const float* Kp=(mode? g_kt : g_k) + (size_t)bI*NIC*NHW + s*96;
  float* Ep=(mode? g_Eh : g_Ew) + (size_t)slab*NHW;
  const int t=threadIdx.x, lane=t&31, grp=lane>>2, tig=lane&3;
  const int warp=t>>5, wm=warp>>2, wn=warp&3;

  float acc[3][3][4];
#pragma unroll
  for(int i=0;i<3;i++)for(int j=0;j<3;j++)for(int r=0;r<4;r++) acc[i][j][r]=0.f;

  for(int c0=0;c0<NIC;c0+=32){
    if(c0) __syncthreads();
#pragma unroll
    for(int i=0;i<6;i++){
      int idx=t+i*256, p=idx/96, w=idx%96;
      int ch=c0+2*p;
      float q0=Qp[(size_t)ch*NHW+w],  q1=Qp[(size_t)(ch+1)*NHW+w];
      float k0v=Kp[(size_t)ch*NHW+w], k1v=Kp[(size_t)(ch+1)*NHW+w];
      unsigned hi,lo;
      split2(q0,q1,hi,lo); Qh[p][w]=hi; Ql[p][w]=lo;
      split2(k0v,k1v,hi,lo); Kh[p][w]=hi; Kl[p][w]=lo;
    }
    __syncthreads();
#pragma unroll
    for(int s2=0;s2<2;s2++){
      const int pb=s2*8;
      unsigned ah[3][4], al[3][4], bh[3][2], bl[3][2];
#pragma unroll
      for(int mt=0;mt<3;mt++){
        int mb=wm*48+mt*16;
        ah[mt][0]=Qh[pb+tig][mb+grp];   ah[mt][1]=Qh[pb+tig][mb+grp+8];
        ah[mt][2]=Qh[pb+tig+4][mb+grp]; ah[mt][3]=Qh[pb+tig+4][mb+grp+8];
        al[mt][0]=Ql[pb+tig][mb+grp];   al[mt][1]=Ql[pb+tig][mb+grp+8];
        al[mt][2]=Ql[pb+tig+4][mb+grp]; al[mt][3]=Ql[pb+tig+4][mb+grp+8];
      }
#pragma unroll
      for(int nt=0;nt<3;nt++){
        int nb=wn*24+nt*8;
        bh[nt][0]=Kh[pb+tig][nb+grp]; bh[nt][1]=Kh[pb+tig+4][nb+grp];
        bl[nt][0]=Kl[pb+tig][nb+grp]; bl[nt][1]=Kl[pb+tig+4][nb+grp];
      }
#pragma unroll
      for(int mt=0;mt<3;mt++)
#pragma unroll
        for(int nt=0;nt<3;nt++){
          mma16h(acc[mt][nt], ah[mt], bh[nt]);
          mma16h(acc[mt][nt], al[mt], bh[nt]);
          mma16h(acc[mt][nt], ah[mt], bl[nt]);
        }
    }
  }
#pragma unroll
  for(int mt=0;mt<3;mt++)
#pragma unroll
    for(int half=0;half<2;half++){
      int row=wm*48+mt*16+grp+half*8;
#pragma unroll
      for(int nt=0;nt<3;nt++){
        int col=wn*24+nt*8+tig*2;
        float2 v; v.x=acc[mt][nt][half*2]; v.y=acc[mt][nt][half*2+1];
        *(float2*)(Ep+(size_t)row*96+col)=v;
      }
    }
}

// ---------------- fused 192-wide softmax -> fp16 A (unchanged) -------------
__global__ __launch_bounds__(256) void softmax_kernel(){
  const int warp=threadIdx.x>>5, lane=threadIdx.x&31;
  const int p=blockIdx.x*8+warp;
  const int bI=p/NHW, rem=p%NHW, h=rem/96, w=rem%96;
  const float* ehp = g_Eh + ((size_t)(bI*96+w)*96 + h)*96;
  const float* ewp = g_Ew + (size_t)p*96;
  __half* ahp = g_Ahh + ((size_t)(bI*96+w)*96 + h)*96;
  __half* awp = g_Awh + (size_t)p*96;
  float eh[3], ew[3], m=-1e30f;
#pragma unroll
  for(int j=0;j<3;j++){
    int g=lane+32*j;
    eh[j]=(g==h)? -1e30f : ehp[g];
    ew[j]=ewp[g];
    m=fmaxf(m,fmaxf(eh[j],ew[j]));
  }
#pragma unroll
  for(int o=16;o>0;o>>=1) m=fmaxf(m,__shfl_xor_sync(0xffffffffu,m,o));
  float sum=0.f;
#pragma unroll
  for(int j=0;j<3;j++){
    eh[j]=__expf(eh[j]-m); ew[j]=__expf(ew[j]-m); sum+=eh[j]+ew[j];
  }
#pragma unroll
  for(int o=16;o>0;o>>=1) sum+=__shfl_xor_sync(0xffffffffu,sum,o);
  float inv=1.f/sum;
#pragma unroll
  for(int j=0;j<3;j++){
    int g=lane+32*j;
    ahp[g]=__float2half((g==h)?0.f:eh[j]*inv);
    awp[g]=__float2half(ew[j]*inv);
  }
}

// ---------------- aggregation: o2 = A_slab(96x96) @ v_slab(96x512) ---------
// grid (2 c-chunks, NB*96 slabs, 2 modes).  Block: 96m x 256n, K=96.
__global__ __launch_bounds__(256) void agg_v(){
  __shared__ unsigned As[24][104];
  __shared__ unsigned Bs[24][264];
  const int nck=blockIdx.x, slab=blockIdx.y, mode=blockIdx.z;
  const int bI=slab/96, s=slab%96, n0=nck*256;
  const __half* Ap=(mode? g_Ahh : g_Awh) + (size_t)slab*NHW;
  const __half* Bb = g_v2 + (mode ? ((size_t)bI*NHW + s)*NC : (size_t)slab*96*NC);
  const size_t rstride = mode ? (size_t)96*NC : (size_t)NC;
  __half* Op=(mode? g_o2h : g_o2w) + (size_t)slab*96*NC;
  const int t=threadIdx.x, lane=t&31, grp=lane>>2, tig=lane&3;
  const int warp=t>>5, wm=warp>>2, wn=warp&3;   // 2m x 4n warps

  float acc[3][8][4];
#pragma unroll
  for(int i=0;i<3;i++)for(int j=0;j<8;j++)for(int r=0;r<4;r++) acc[i][j][r]=0.f;

  for(int kc=0;kc<96;kc+=48){
    if(kc) __syncthreads();
#pragma unroll
    for(int i=0;i<9;i++){
      int idx=t+i*256, m=idx/24, kp=idx%24;
      As[kp][m]=*(const unsigned*)(Ap + (size_t)m*96 + kc + 2*kp);
    }
#pragma unroll
    for(int i=0;i<12;i++){
      int idx=t+i*256, kp=idx/128, nj=idx%128;
      const __half* r0=Bb + (size_t)(kc+2*kp)*rstride + n0 + 2*nj;
      unsigned u0=*(const unsigned*)r0;
      unsigned u1=*(const unsigned*)(r0+rstride);
      Bs[kp][2*nj]  =(u0&0xffffu)|(u1<<16);
      Bs[kp][2*nj+1]=(u0>>16)|(u1&0xffff0000u);
    }
    __syncthreads();
#pragma unroll
    for(int s2=0;s2<3;s2++){
      const int pb=s2*8;
      unsigned a[3][4], b[8][2];
#pragma unroll
      for(int mt=0;mt<3;mt++){
        int mb=wm*48+mt*16;
        a[mt][0]=As[pb+tig][mb+grp];   a[mt][1]=As[pb+tig][mb+grp+8];
        a[mt][2]=As[pb+tig+4][mb+grp]; a[mt][3]=As[pb+tig+4][mb+grp+8];
      }
#pragma unroll
      for(int nt=0;nt<8;nt++){
        int nb=wn*64+nt*8;
        b[nt][0]=Bs[pb+tig][nb+grp]; b[nt][1]=Bs[pb+tig+4][nb+grp];
      }
#pragma unroll
      for(int mt=0;mt<3;mt++)
#pragma unroll
        for(int nt=0;nt<8;nt++) mma16h(acc[mt][nt], a[mt], b[nt]);
    }
  }
#pragma unroll
  for(int mt=0;mt<3;mt++)
#pragma unroll
    for(int half=0;half<2;half++){
      int m=wm*48+mt*16+grp+half*8;
#pragma unroll
      for(int nt=0;nt<8;nt++){
        int col=n0+wn*64+nt*8+tig*2;
        *(__half2*)(Op + (size_t)m*NC + col) =
            __floats2half2_rn(acc[mt][nt][half*2], acc[mt][nt][half*2+1]);
      }
    }
}

// ---------------- combine: out = gamma*(o2w + o2h^T + bv) + x --------------
// grid (8 c-chunks, 96 h, NB).  smem pivot channel-minor -> channel-major.
__global__ __launch_bounds__(256) void combine_kernel(
  const float* __restrict__ bv, const float* __restrict__ gamma,
  const float* __restrict__ x, float* __restrict__ out)
{
  __shared__ float s[96][65];
  const int c0=blockIdx.x*64, h=blockIdx.y, bI=blockIdx.z;
  const int t=threadIdx.x;
  const float gam=gamma[0];
#pragma unroll
  for(int i=0;i<12;i++){
    int idx=t+i*256, w=idx/32, cj=idx%32;
    __half2 aw=*(const __half2*)(g_o2w + ((size_t)(bI*96+h)*96+w)*NC + c0 + 2*cj);
    __half2 ah=*(const __half2*)(g_o2h + ((size_t)(bI*96+w)*96+h)*NC + c0 + 2*cj);
    float2 fa=__half22float2(aw), fb=__half22float2(ah);
    s[w][2*cj]=fa.x+fb.x; s[w][2*cj+1]=fa.y+fb.y;
  }
  __syncthreads();
#pragma unroll
  for(int i=0;i<24;i++){
    int idx=t+i*256, c=idx/96, w=idx%96;
    size_t a=((size_t)bI*NC + c0+c)*NHW + (size_t)h*96 + w;
    out[a]=gam*(s[w][c]+bv[c0+c])+x[a];
  }
}

// ---------------- launch ----------------------------------------------------
extern "C" void kernel_launch(void* const* d_in, const int* in_sizes, int n_in,
                              void* d_out, int out_size){
  const float* x    =(const float*)d_in[0];
  const float* Wq   =(const float*)d_in[1];
  const float* bq   =(const float*)d_in[2];
  const float* Wk   =(const float*)d_in[3];
  const float* bk   =(const float*)d_in[4];
  const float* Wv   =(const float*)d_in[5];
  const float* bv   =(const float*)d_in[6];
  const float* gamma=(const float*)d_in[7];
  float* out=(float*)d_out;

  gemm_qkv<<<dim3(NHW/128,5,NB),256>>>(x,Wq,bq,Wk,bk,Wv);
  transpose_qk<<<dim3(NB*NIC,2),256>>>();
  logits_kernel<<<dim3(NB*96,2),256>>>();
  softmax_kernel<<<NB*NHW/8,256>>>();
  agg_v<<<dim3(2,NB*96,2),256>>>();
  combine_kernel<<<dim3(8,96,NB),256>>>(bv,gamma,x,out);
}

// round 9
// speedup vs baseline: 1.5971x; 1.0125x over previous
#include <cuda_runtime.h>
#include <cuda_fp16.h>
#include <cstdint>
#include <cstddef>

#define NB 8
#define NC 512
#define NIC 64
#define NHW 9216

// ---------------- scratch (device globals; no runtime allocation) ----------
__device__ float g_q [NB*NIC*NHW];
__device__ float g_k [NB*NIC*NHW];
__device__ float g_qt[NB*NIC*NHW];
__device__ float g_kt[NB*NIC*NHW];
__device__ float g_Ew[(size_t)NB*NHW*96];      // [b][h][w][v] row logits
__device__ float g_Eh[(size_t)NB*NHW*96];      // [b][w][h][g] col logits
__device__ __half g_Awh[(size_t)NB*NHW*96];    // softmax row part [b][h][w][v]
__device__ __half g_Ahh[(size_t)NB*NHW*96];    // softmax col part [b][w][h][g]
__device__ __half g_v2 [(size_t)NB*NHW*NC];    // v = Wv@x, channel-minor [b][h][w][c]
__device__ __half g_o2w[(size_t)NB*NHW*NC];    // row-agg out [b][h][w][c]
__device__ __half g_o2h[(size_t)NB*NHW*NC];    // col-agg out [b][w][h][c]

// ---------------- helpers ---------------------------------------------------
__device__ __forceinline__ void mma16h(float* d, const unsigned* a, const unsigned* b){
  asm volatile("mma.sync.aligned.m16n8k16.row.col.f32.f16.f16.f32 "
    "{%0,%1,%2,%3},{%4,%5,%6,%7},{%8,%9},{%0,%1,%2,%3};\n"
    :"+f"(d[0]),"+f"(d[1]),"+f"(d[2]),"+f"(d[3])
    :"r"(a[0]),"r"(a[1]),"r"(a[2]),"r"(a[3]),"r"(b[0]),"r"(b[1]));
}
__device__ __forceinline__ unsigned packh2(float a, float b){
  __half2 v=__floats2half2_rn(a,b); return *reinterpret_cast<unsigned*>(&v);
}
__device__ __forceinline__ void split2(float v0, float v1, unsigned& hi, unsigned& lo){
  __half h0=__float2half_rn(v0), h1=__float2half_rn(v1);
  float  r0=v0-__half2float(h0), r1=v1-__half2float(h1);
  __half2 hv=__halves2half2(h0,h1);
  __half2 lv=__floats2half2_rn(r0,r1);
  hi=*reinterpret_cast<unsigned*>(&hv);
  lo=*reinterpret_cast<unsigned*>(&lv);
}

// ---------------- q/k projection: [Wq;Wk](128x512) @ x_b, split-fp16 -------
// Software-pipelined: B (x) chunk k+1 prefetched into registers during mma k.
__global__ __launch_bounds__(256,2) void gemm_qk(
  const float* __restrict__ x,
  const float* __restrict__ Wq, const float* __restrict__ bq,
  const float* __restrict__ Wk, const float* __restrict__ bk)
{
  __shared__ unsigned Ahs[16][136], Als[16][136], Bhs[16][136], Bls[16][136];
  const int bI=blockIdx.y, n0=blockIdx.x*128;
  const float* Bp = x + (size_t)bI*NC*NHW;
  const int t=threadIdx.x, lane=t&31, grp=lane>>2, tig=lane&3;
  const int warp=t>>5, wm=warp>>2, wn=warp&3;

  float acc[4][4][4];
#pragma unroll
  for(int i=0;i<4;i++)for(int j=0;j<4;j++)for(int r=0;r<4;r++) acc[i][j][r]=0.f;

  const int am=t&127, aks=(t>>7)*16;
  const float* Ar = (am<64)? Wq+(size_t)am*NC : Wk+(size_t)(am-64)*NC;
  const int bn=t&127, bkp=(t>>7)*8;

  float fb0[8], fb1[8];
#pragma unroll
  for(int j=0;j<8;j++){
    int row=2*(bkp+j);
    fb0[j]=Bp[(size_t)row*NHW+n0+bn];
    fb1[j]=Bp[(size_t)(row+1)*NHW+n0+bn];
  }

  for(int k0=0;k0<NC;k0+=32){
    float av[16];
#pragma unroll
    for(int i=0;i<4;i++) *(float4*)(av+4*i)=*(const float4*)(Ar+k0+aks+4*i);
    if(k0) __syncthreads();
#pragma unroll
    for(int j=0;j<8;j++){
      unsigned hi,lo; split2(av[2*j],av[2*j+1],hi,lo);
      Ahs[aks/2+j][am]=hi; Als[aks/2+j][am]=lo;
    }
#pragma unroll
    for(int j=0;j<8;j++){
      unsigned hi,lo; split2(fb0[j],fb1[j],hi,lo);
      Bhs[bkp+j][bn]=hi; Bls[bkp+j][bn]=lo;
    }
    __syncthreads();
    if(k0+32<NC){
#pragma unroll
      for(int j=0;j<8;j++){
        int row=k0+32+2*(bkp+j);
        fb0[j]=Bp[(size_t)row*NHW+n0+bn];
        fb1[j]=Bp[(size_t)(row+1)*NHW+n0+bn];
      }
    }
#pragma unroll
    for(int s=0;s<2;s++){
      const int pb=s*8;
      unsigned ah[4][4], al[4][4], bh[4][2], bl[4][2];
#pragma unroll
      for(int mt=0;mt<4;mt++){
        int mb=wm*64+mt*16;
        ah[mt][0]=Ahs[pb+tig][mb+grp];   ah[mt][1]=Ahs[pb+tig][mb+grp+8];
        ah[mt][2]=Ahs[pb+tig+4][mb+grp]; ah[mt][3]=Ahs[pb+tig+4][mb+grp+8];
        al[mt][0]=Als[pb+tig][mb+grp];   al[mt][1]=Als[pb+tig][mb+grp+8];
        al[mt][2]=Als[pb+tig+4][mb+grp]; al[mt][3]=Als[pb+tig+4][mb+grp+8];
      }
#pragma unroll
      for(int nt=0;nt<4;nt++){
        int nb=wn*32+nt*8;
        bh[nt][0]=Bhs[pb+tig][nb+grp]; bh[nt][1]=Bhs[pb+tig+4][nb+grp];
        bl[nt][0]=Bls[pb+tig][nb+grp]; bl[nt][1]=Bls[pb+tig+4][nb+grp];
      }
#pragma unroll
      for(int mt=0;mt<4;mt++)
#pragma unroll
        for(int nt=0;nt<4;nt++){
          mma16h(acc[mt][nt], ah[mt], bh[nt]);
          mma16h(acc[mt][nt], al[mt], bh[nt]);
          mma16h(acc[mt][nt], ah[mt], bl[nt]);
        }
    }
  }
#pragma unroll
  for(int mt=0;mt<4;mt++)
#pragma unroll
    for(int half=0;half<2;half++){
      int rr=wm*64+mt*16+grp+half*8;
      float bias; float* dst;
      if(rr<64){bias=bq[rr]; dst=g_q+((size_t)bI*NIC+rr)*NHW;}
      else     {bias=bk[rr-64]; dst=g_k+((size_t)bI*NIC+(rr-64))*NHW;}
#pragma unroll
      for(int nt=0;nt<4;nt++){
        int cc=n0+wn*32+nt*8+tig*2;
        float2 v; v.x=acc[mt][nt][half*2]+bias; v.y=acc[mt][nt][half*2+1]+bias;
        *(float2*)(dst+cc)=v;
      }
    }
}

// ---------------- v projection: Wv(512x512) @ x_b -> v2 channel-minor ------
// Software-pipelined: A and B chunk k+1 prefetched during mma k.
// NOTE: sbuf must be 4*16*136 words (34816 B) — the epilogue reuses it as a
// 128x136 __half transpose tile even though the mainloop needs only 2 tiles.
__global__ __launch_bounds__(256,2) void gemm_v(
  const float* __restrict__ x, const float* __restrict__ Wv)
{
  __shared__ __align__(16) unsigned sbuf[4*16*136];
  unsigned (*Ahs)[136] = (unsigned(*)[136])(sbuf);
  unsigned (*Bhs)[136] = (unsigned(*)[136])(sbuf+2176);

  const int bI=blockIdx.z, n0=blockIdx.x*128, m0v=blockIdx.y*128;
  const float* Bp = x + (size_t)bI*NC*NHW;
  const int t=threadIdx.x, lane=t&31, grp=lane>>2, tig=lane&3;
  const int warp=t>>5, wm=warp>>2, wn=warp&3;

  float acc[4][4][4];
#pragma unroll
  for(int i=0;i<4;i++)for(int j=0;j<4;j++)for(int r=0;r<4;r++) acc[i][j][r]=0.f;

  const int am=t&127, aks=(t>>7)*16;
  const float* Ar = Wv + (size_t)(m0v+am)*NC;
  const int bn=t&127, bkp=(t>>7)*8;

  float fa[16], fb0[8], fb1[8];
#pragma unroll
  for(int i=0;i<4;i++) *(float4*)(fa+4*i)=*(const float4*)(Ar+aks+4*i);
#pragma unroll
  for(int j=0;j<8;j++){
    int row=2*(bkp+j);
    fb0[j]=Bp[(size_t)row*NHW+n0+bn];
    fb1[j]=Bp[(size_t)(row+1)*NHW+n0+bn];
  }

  for(int k0=0;k0<NC;k0+=32){
    if(k0) __syncthreads();
#pragma unroll
    for(int j=0;j<8;j++) Ahs[aks/2+j][am]=packh2(fa[2*j],fa[2*j+1]);
#pragma unroll
    for(int j=0;j<8;j++) Bhs[bkp+j][bn]=packh2(fb0[j],fb1[j]);
    __syncthreads();
    if(k0+32<NC){
#pragma unroll
      for(int i=0;i<4;i++) *(float4*)(fa+4*i)=*(const float4*)(Ar+k0+32+aks+4*i);
#pragma unroll
      for(int j=0;j<8;j++){
        int row=k0+32+2*(bkp+j);
        fb0[j]=Bp[(size_t)row*NHW+n0+bn];
        fb1[j]=Bp[(size_t)(row+1)*NHW+n0+bn];
      }
    }
#pragma unroll
    for(int s=0;s<2;s++){
      const int pb=s*8;
      unsigned a[4][4], b[4][2];
#pragma unroll
      for(int mt=0;mt<4;mt++){
        int mb=wm*64+mt*16;
        a[mt][0]=Ahs[pb+tig][mb+grp];   a[mt][1]=Ahs[pb+tig][mb+grp+8];
        a[mt][2]=Ahs[pb+tig+4][mb+grp]; a[mt][3]=Ahs[pb+tig+4][mb+grp+8];
      }
#pragma unroll
      for(int nt=0;nt<4;nt++){
        int nb=wn*32+nt*8;
        b[nt][0]=Bhs[pb+tig][nb+grp]; b[nt][1]=Bhs[pb+tig+4][nb+grp];
      }
#pragma unroll
      for(int mt=0;mt<4;mt++)
#pragma unroll
        for(int nt=0;nt<4;nt++) mma16h(acc[mt][nt], a[mt], b[nt]);
    }
  }
  // epilogue: transpose 128m(c) x 128n(pix) tile through smem, write v2
  __syncthreads();
  __half (*st)[136] = (__half(*)[136])sbuf;
#pragma unroll
  for(int mt=0;mt<4;mt++)
#pragma unroll
    for(int half=0;half<2;half++){
      int m=wm*64+mt*16+grp+half*8;
#pragma unroll
      for(int nt=0;nt<4;nt++){
        int n=wn*32+nt*8+tig*2;
        st[n][m]  =__float2half(acc[mt][nt][half*2]);
        st[n+1][m]=__float2half(acc[mt][nt][half*2+1]);
      }
    }
  __syncthreads();
  __half2* v2p=(__half2*)(g_v2 + ((size_t)bI*NHW + n0)*NC + m0v);
#pragma unroll
  for(int i=0;i<32;i++){
    int lin=i*256+t, p=lin>>6, cj=lin&63;
    v2p[(size_t)p*(NC/2)+cj] = *(__half2*)&st[p][2*cj];
  }
}

// ---------------- fp32 96x96 transpose for q,k ------------------------------
__global__ __launch_bounds__(256) void transpose_qk(){
  __shared__ float s[96][97];
  const float* in  = blockIdx.y ? g_k  : g_q;
  float*       out = blockIdx.y ? g_kt : g_qt;
  size_t base=(size_t)blockIdx.x*NHW;
  int t=threadIdx.x;
#pragma unroll
  for(int i=0;i<36;i++){int idx=t+i*256; s[idx/96][idx%96]=in[base+idx];}
  __syncthreads();
#pragma unroll
  for(int i=0;i<36;i++){int idx=t+i*256; out[base+idx]=s[idx%96][idx/96];}
}

// ---------------- logits (unchanged) ----------------------------------------
__global__ __launch_bounds__(256) void logits_kernel(){
  __shared__ unsigned Qh[16][104], Ql[16][104], Kh[16][104], Kl[16][104];
  const int slab=blockIdx.x, mode=blockIdx.y;
  const int bI=slab/96, s=slab%96;
  const float* Qp=(mode? g_qt : g_q) + (size_t)bI*NIC*NHW + s*96;
  const float* Kp=(mode? g_kt : g_k) + (size_t)bI*NIC*NHW + s*96;
  float* Ep=(mode? g_Eh : g_Ew) + (size_t)slab*NHW;
  const int t=threadIdx.x, lane=t&31, grp=lane>>2, tig=lane&3;
  const int warp=t>>5, wm=warp>>2, wn=warp&3;

  float acc[3][3][4];
#pragma unroll
  for(int i=0;i<3;i++)for(int j=0;j<3;j++)for(int r=0;r<4;r++) acc[i][j][r]=0.f;

  for(int c0=0;c0<NIC;c0+=32){
    if(c0) __syncthreads();
#pragma unroll
    for(int i=0;i<6;i++){
      int idx=t+i*256, p=idx/96, w=idx%96;
      int ch=c0+2*p;
      float q0=Qp[(size_t)ch*NHW+w],  q1=Qp[(size_t)(ch+1)*NHW+w];
      float k0v=Kp[(size_t)ch*NHW+w], k1v=Kp[(size_t)(ch+1)*NHW+w];
      unsigned hi,lo;
      split2(q0,q1,hi,lo); Qh[p][w]=hi; Ql[p][w]=lo;
      split2(k0v,k1v,hi,lo); Kh[p][w]=hi; Kl[p][w]=lo;
    }
    __syncthreads();
#pragma unroll
    for(int s2=0;s2<2;s2++){
      const int pb=s2*8;
      unsigned ah[3][4], al[3][4], bh[3][2], bl[3][2];
#pragma unroll
      for(int mt=0;mt<3;mt++){
        int mb=wm*48+mt*16;
        ah[mt][0]=Qh[pb+tig][mb+grp];   ah[mt][1]=Qh[pb+tig][mb+grp+8];
        ah[mt][2]=Qh[pb+tig+4][mb+grp]; ah[mt][3]=Qh[pb+tig+4][mb+grp+8];
        al[mt][0]=Ql[pb+tig][mb+grp];   al[mt][1]=Ql[pb+tig][mb+grp+8];
        al[mt][2]=Ql[pb+tig+4][mb+grp]; al[mt][3]=Ql[pb+tig+4][mb+grp+8];
      }
#pragma unroll
      for(int nt=0;nt<3;nt++){
        int nb=wn*24+nt*8;
        bh[nt][0]=Kh[pb+tig][nb+grp]; bh[nt][1]=Kh[pb+tig+4][nb+grp];
        bl[nt][0]=Kl[pb+tig][nb+grp]; bl[nt][1]=Kl[pb+tig+4][nb+grp];
      }
#pragma unroll
      for(int mt=0;mt<3;mt++)
#pragma unroll
        for(int nt=0;nt<3;nt++){
          mma16h(acc[mt][nt], ah[mt], bh[nt]);
          mma16h(acc[mt][nt], al[mt], bh[nt]);
          mma16h(acc[mt][nt], ah[mt], bl[nt]);
        }
    }
  }
#pragma unroll
  for(int mt=0;mt<3;mt++)
#pragma unroll
    for(int half=0;half<2;half++){
      int row=wm*48+mt*16+grp+half*8;
#pragma unroll
      for(int nt=0;nt<3;nt++){
        int col=wn*24+nt*8+tig*2;
        float2 v; v.x=acc[mt][nt][half*2]; v.y=acc[mt][nt][half*2+1];
        *(float2*)(Ep+(size_t)row*96+col)=v;
      }
    }
}

// ---------------- fused 192-wide softmax -> fp16 A (unchanged) -------------
__global__ __launch_bounds__(256) void softmax_kernel(){
  const int warp=threadIdx.x>>5, lane=threadIdx.x&31;
  const int p=blockIdx.x*8+warp;
  const int bI=p/NHW, rem=p%NHW, h=rem/96, w=rem%96;
  const float* ehp = g_Eh + ((size_t)(bI*96+w)*96 + h)*96;
  const float* ewp = g_Ew + (size_t)p*96;
  __half* ahp = g_Ahh + ((size_t)(bI*96+w)*96 + h)*96;
  __half* awp = g_Awh + (size_t)p*96;
  float eh[3], ew[3], m=-1e30f;
#pragma unroll
  for(int j=0;j<3;j++){
    int g=lane+32*j;
    eh[j]=(g==h)? -1e30f : ehp[g];
    ew[j]=ewp[g];
    m=fmaxf(m,fmaxf(eh[j],ew[j]));
  }
#pragma unroll
  for(int o=16;o>0;o>>=1) m=fmaxf(m,__shfl_xor_sync(0xffffffffu,m,o));
  float sum=0.f;
#pragma unroll
  for(int j=0;j<3;j++){
    eh[j]=__expf(eh[j]-m); ew[j]=__expf(ew[j]-m); sum+=eh[j]+ew[j];
  }
#pragma unroll
  for(int o=16;o>0;o>>=1) sum+=__shfl_xor_sync(0xffffffffu,sum,o);
  float inv=1.f/sum;
#pragma unroll
  for(int j=0;j<3;j++){
    int g=lane+32*j;
    ahp[g]=__float2half((g==h)?0.f:eh[j]*inv);
    awp[g]=__float2half(ew[j]*inv);
  }
}

// ---------------- aggregation (unchanged): o2 = A_slab @ v_slab ------------
__global__ __launch_bounds__(256) void agg_v(){
  __shared__ unsigned As[24][104];
  __shared__ unsigned Bs[24][264];
  const int nck=blockIdx.x, slab=blockIdx.y, mode=blockIdx.z;
  const int bI=slab/96, s=slab%96, n0=nck*256;
  const __half* Ap=(mode? g_Ahh : g_Awh) + (size_t)slab*NHW;
  const __half* Bb = g_v2 + (mode ? ((size_t)bI*NHW + s)*NC : (size_t)slab*96*NC);
  const size_t rstride = mode ? (size_t)96*NC : (size_t)NC;
  __half* Op=(mode? g_o2h : g_o2w) + (size_t)slab*96*NC;
  const int t=threadIdx.x, lane=t&31, grp=lane>>2, tig=lane&3;
  const int warp=t>>5, wm=warp>>2, wn=warp&3;

  float acc[3][8][4];
#pragma unroll
  for(int i=0;i<3;i++)for(int j=0;j<8;j++)for(int r=0;r<4;r++) acc[i][j][r]=0.f;

  for(int kc=0;kc<96;kc+=48){
    if(kc) __syncthreads();
#pragma unroll
    for(int i=0;i<9;i++){
      int idx=t+i*256, m=idx/24, kp=idx%24;
      As[kp][m]=*(const unsigned*)(Ap + (size_t)m*96 + kc + 2*kp);
    }
#pragma unroll
    for(int i=0;i<12;i++){
      int idx=t+i*256, kp=idx/128, nj=idx%128;
      const __half* r0=Bb + (size_t)(kc+2*kp)*rstride + n0 + 2*nj;
      unsigned u0=*(const unsigned*)r0;
      unsigned u1=*(const unsigned*)(r0+rstride);
      Bs[kp][2*nj]  =(u0&0xffffu)|(u1<<16);
      Bs[kp][2*nj+1]=(u0>>16)|(u1&0xffff0000u);
    }
    __syncthreads();
#pragma unroll
    for(int s2=0;s2<3;s2++){
      const int pb=s2*8;
      unsigned a[3][4], b[8][2];
#pragma unroll
      for(int mt=0;mt<3;mt++){
        int mb=wm*48+mt*16;
        a[mt][0]=As[pb+tig][mb+grp];   a[mt][1]=As[pb+tig][mb+grp+8];
        a[mt][2]=As[pb+tig+4][mb+grp]; a[mt][3]=As[pb+tig+4][mb+grp+8];
      }
#pragma unroll
      for(int nt=0;nt<8;nt++){
        int nb=wn*64+nt*8;
        b[nt][0]=Bs[pb+tig][nb+grp]; b[nt][1]=Bs[pb+tig+4][nb+grp];
      }
#pragma unroll
      for(int mt=0;mt<3;mt++)
#pragma unroll
        for(int nt=0;nt<8;nt++) mma16h(acc[mt][nt], a[mt], b[nt]);
    }
  }
#pragma unroll
  for(int mt=0;mt<3;mt++)
#pragma unroll
    for(int half=0;half<2;half++){
      int m=wm*48+mt*16+grp+half*8;
#pragma unroll
      for(int nt=0;nt<8;nt++){
        int col=n0+wn*64+nt*8+tig*2;
        *(__half2*)(Op + (size_t)m*NC + col) =
            __floats2half2_rn(acc[mt][nt][half*2], acc[mt][nt][half*2+1]);
      }
    }
}

// ---------------- combine (unchanged): out = gamma*(o2w + o2h^T + bv) + x --
__global__ __launch_bounds__(256) void combine_kernel(
  const float* __restrict__ bv, const float* __restrict__ gamma,
  const float* __restrict__ x, float* __restrict__ out)
{
  __shared__ float s[96][65];
  const int c0=blockIdx.x*64, h=blockIdx.y, bI=blockIdx.z;
  const int t=threadIdx.x;
  const float gam=gamma[0];
#pragma unroll
  for(int i=0;i<12;i++){
    int idx=t+i*256, w=idx/32, cj=idx%32;
    __half2 aw=*(const __half2*)(g_o2w + ((size_t)(bI*96+h)*96+w)*NC + c0 + 2*cj);
    __half2 ah=*(const __half2*)(g_o2h + ((size_t)(bI*96+w)*96+h)*NC + c0 + 2*cj);
    float2 fa=__half22float2(aw), fb=__half22float2(ah);
    s[w][2*cj]=fa.x+fb.x; s[w][2*cj+1]=fa.y+fb.y;
  }
  __syncthreads();
#pragma unroll
  for(int i=0;i<24;i++){
    int idx=t+i*256, c=idx/96, w=idx%96;
    size_t a=((size_t)bI*NC + c0+c)*NHW + (size_t)h*96 + w;
    out[a]=gam*(s[w][c]+bv[c0+c])+x[a];
  }
}

// ---------------- launch ----------------------------------------------------
extern "C" void kernel_launch(void* const* d_in, const int* in_sizes, int n_in,
                              void* d_out, int out_size){
  const float* x    =(const float*)d_in[0];
  const float* Wq   =(const float*)d_in[1];
  const float* bq   =(const float*)d_in[2];
  const float* Wk   =(const float*)d_in[3];
  const float* bk   =(const float*)d_in[4];
  const float* Wv   =(const float*)d_in[5];
  const float* bv   =(const float*)d_in[6];
  const float* gamma=(const float*)d_in[7];
  float* out=(float*)d_out;

  gemm_qk<<<dim3(NHW/128,NB),256>>>(x,Wq,bq,Wk,bk);
  gemm_v<<<dim3(NHW/128,4,NB),256>>>(x,Wv);
  transpose_qk<<<dim3(NB*NIC,2),256>>>();
  logits_kernel<<<dim3(NB*96,2),256>>>();
  softmax_kernel<<<NB*NHW/8,256>>>();
  agg_v<<<dim3(2,NB*96,2),256>>>();
  combine_kernel<<<dim3(8,96,NB),256>>>(bv,gamma,x,out);
}

// round 11
// speedup vs baseline: 1.6106x; 1.0085x over previous
#include <cuda_runtime.h>
#include <cuda_fp16.h>
#include <cstdint>
#include <cstddef>

#define NB 8
#define NC 512
#define NIC 64
#define NHW 9216

// ---------------- scratch (device globals; no runtime allocation) ----------
__device__ float g_q [NB*NIC*NHW];
__device__ float g_k [NB*NIC*NHW];
__device__ float g_qt[NB*NIC*NHW];
__device__ float g_kt[NB*NIC*NHW];
__device__ __half g_Ewh[(size_t)NB*NHW*96];   // row logits  [b][h][w][v], fp16
__device__ __half g_Ehh[(size_t)NB*NHW*96];   // col logits  [b][w][h][g], fp16
__device__ __half g_Awh[(size_t)NB*NHW*96];   // softmax row part
__device__ __half g_Ahh[(size_t)NB*NHW*96];   // softmax col part (transposed layout)
__device__ __half g_v2 [(size_t)NB*NHW*NC];   // v = Wv@x, channel-minor [b][h][w][c]
__device__ __half g_o2 [(size_t)NB*NHW*NC];   // combined agg out [b][h][w][c]

// ---------------- helpers ---------------------------------------------------
__device__ __forceinline__ void mma16h(float* d, const unsigned* a, const unsigned* b){
  asm volatile("mma.sync.aligned.m16n8k16.row.col.f32.f16.f16.f32 "
    "{%0,%1,%2,%3},{%4,%5,%6,%7},{%8,%9},{%0,%1,%2,%3};\n"
    :"+f"(d[0]),"+f"(d[1]),"+f"(d[2]),"+f"(d[3])
    :"r"(a[0]),"r"(a[1]),"r"(a[2]),"r"(a[3]),"r"(b[0]),"r"(b[1]));
}
__device__ __forceinline__ unsigned packh2(float a, float b){
  __half2 v=__floats2half2_rn(a,b); return *reinterpret_cast<unsigned*>(&v);
}
__device__ __forceinline__ void split2(float v0, float v1, unsigned& hi, unsigned& lo){
  __half h0=__float2half_rn(v0), h1=__float2half_rn(v1);
  float  r0=v0-__half2float(h0), r1=v1-__half2float(h1);
  __half2 hv=__halves2half2(h0,h1);
  __half2 lv=__floats2half2_rn(r0,r1);
  hi=*reinterpret_cast<unsigned*>(&hv);
  lo=*reinterpret_cast<unsigned*>(&lv);
}
__device__ __forceinline__ void red_h2(__half2* p, __half2 v){
  asm volatile("red.global.add.noftz.f16x2 [%0], %1;"
    ::"l"(p),"r"(*reinterpret_cast<unsigned*>(&v)):"memory");
}

// ---------------- q/k projection: [Wq;Wk](128x512) @ x_b, split-fp16 -------
__global__ __launch_bounds__(256,2) void gemm_qk(
  const float* __restrict__ x,
  const float* __restrict__ Wq, const float* __restrict__ bq,
  const float* __restrict__ Wk, const float* __restrict__ bk)
{
  __shared__ unsigned Ahs[16][136], Als[16][136], Bhs[16][136], Bls[16][136];
  const int bI=blockIdx.y, n0=blockIdx.x*128;
  const float* Bp = x + (size_t)bI*NC*NHW;
  const int t=threadIdx.x, lane=t&31, grp=lane>>2, tig=lane&3;
  const int warp=t>>5, wm=warp>>2, wn=warp&3;

  float acc[4][4][4];
#pragma unroll
  for(int i=0;i<4;i++)for(int j=0;j<4;j++)for(int r=0;r<4;r++) acc[i][j][r]=0.f;

  const int am=t&127, aks=(t>>7)*16;
  const float* Ar = (am<64)? Wq+(size_t)am*NC : Wk+(size_t)(am-64)*NC;
  const int bn=t&127, bkp=(t>>7)*8;

  float fb0[8], fb1[8];
#pragma unroll
  for(int j=0;j<8;j++){
    int row=2*(bkp+j);
    fb0[j]=Bp[(size_t)row*NHW+n0+bn];
    fb1[j]=Bp[(size_t)(row+1)*NHW+n0+bn];
  }

  for(int k0=0;k0<NC;k0+=32){
    float av[16];
#pragma unroll
    for(int i=0;i<4;i++) *(float4*)(av+4*i)=*(const float4*)(Ar+k0+aks+4*i);
    if(k0) __syncthreads();
#pragma unroll
    for(int j=0;j<8;j++){
      unsigned hi,lo; split2(av[2*j],av[2*j+1],hi,lo);
      Ahs[aks/2+j][am]=hi; Als[aks/2+j][am]=lo;
    }
#pragma unroll
    for(int j=0;j<8;j++){
      unsigned hi,lo; split2(fb0[j],fb1[j],hi,lo);
      Bhs[bkp+j][bn]=hi; Bls[bkp+j][bn]=lo;
    }
    __syncthreads();
    if(k0+32<NC){
#pragma unroll
      for(int j=0;j<8;j++){
        int row=k0+32+2*(bkp+j);
        fb0[j]=Bp[(size_t)row*NHW+n0+bn];
        fb1[j]=Bp[(size_t)(row+1)*NHW+n0+bn];
      }
    }
#pragma unroll
    for(int s=0;s<2;s++){
      const int pb=s*8;
      unsigned ah[4][4], al[4][4], bh[4][2], bl[4][2];
#pragma unroll
      for(int mt=0;mt<4;mt++){
        int mbx=wm*64+mt*16;
        ah[mt][0]=Ahs[pb+tig][mbx+grp];   ah[mt][1]=Ahs[pb+tig][mbx+grp+8];
        ah[mt][2]=Ahs[pb+tig+4][mbx+grp]; ah[mt][3]=Ahs[pb+tig+4][mbx+grp+8];
        al[mt][0]=Als[pb+tig][mbx+grp];   al[mt][1]=Als[pb+tig][mbx+grp+8];
        al[mt][2]=Als[pb+tig+4][mbx+grp]; al[mt][3]=Als[pb+tig+4][mbx+grp+8];
      }
#pragma unroll
      for(int nt=0;nt<4;nt++){
        int nb=wn*32+nt*8;
        bh[nt][0]=Bhs[pb+tig][nb+grp]; bh[nt][1]=Bhs[pb+tig+4][nb+grp];
        bl[nt][0]=Bls[pb+tig][nb+grp]; bl[nt][1]=Bls[pb+tig+4][nb+grp];
      }
#pragma unroll
      for(int mt=0;mt<4;mt++)
#pragma unroll
        for(int nt=0;nt<4;nt++){
          mma16h(acc[mt][nt], ah[mt], bh[nt]);
          mma16h(acc[mt][nt], al[mt], bh[nt]);
          mma16h(acc[mt][nt], ah[mt], bl[nt]);
        }
    }
  }
#pragma unroll
  for(int mt=0;mt<4;mt++)
#pragma unroll
    for(int half=0;half<2;half++){
      int rr=wm*64+mt*16+grp+half*8;
      float bias; float* dst;
      if(rr<64){bias=bq[rr]; dst=g_q+((size_t)bI*NIC+rr)*NHW;}
      else     {bias=bk[rr-64]; dst=g_k+((size_t)bI*NIC+(rr-64))*NHW;}
#pragma unroll
      for(int nt=0;nt<4;nt++){
        int cc=n0+wn*32+nt*8+tig*2;
        float2 v; v.x=acc[mt][nt][half*2]+bias; v.y=acc[mt][nt][half*2+1]+bias;
        *(float2*)(dst+cc)=v;
      }
    }
}

// ---------------- v projection: Wv(512x512) @ x_b -> v2 channel-minor ------
__global__ __launch_bounds__(256,2) void gemm_v(
  const float* __restrict__ x, const float* __restrict__ Wv)
{
  __shared__ __align__(16) unsigned sbuf[4*16*136];
  unsigned (*Ahs)[136] = (unsigned(*)[136])(sbuf);
  unsigned (*Bhs)[136] = (unsigned(*)[136])(sbuf+2176);

  const int bI=blockIdx.z, n0=blockIdx.x*128, m0v=blockIdx.y*128;
  const float* Bp = x + (size_t)bI*NC*NHW;
  const int t=threadIdx.x, lane=t&31, grp=lane>>2, tig=lane&3;
  const int warp=t>>5, wm=warp>>2, wn=warp&3;

  float acc[4][4][4];
#pragma unroll
  for(int i=0;i<4;i++)for(int j=0;j<4;j++)for(int r=0;r<4;r++) acc[i][j][r]=0.f;

  const int am=t&127, aks=(t>>7)*16;
  const float* Ar = Wv + (size_t)(m0v+am)*NC;
  const int bn=t&127, bkp=(t>>7)*8;

  float fa[16], fb0[8], fb1[8];
#pragma unroll
  for(int i=0;i<4;i++) *(float4*)(fa+4*i)=*(const float4*)(Ar+aks+4*i);
#pragma unroll
  for(int j=0;j<8;j++){
    int row=2*(bkp+j);
    fb0[j]=Bp[(size_t)row*NHW+n0+bn];
    fb1[j]=Bp[(size_t)(row+1)*NHW+n0+bn];
  }

  for(int k0=0;k0<NC;k0+=32){
    if(k0) __syncthreads();
#pragma unroll
    for(int j=0;j<8;j++) Ahs[aks/2+j][am]=packh2(fa[2*j],fa[2*j+1]);
#pragma unroll
    for(int j=0;j<8;j++) Bhs[bkp+j][bn]=packh2(fb0[j],fb1[j]);
    __syncthreads();
    if(k0+32<NC){
#pragma unroll
      for(int i=0;i<4;i++) *(float4*)(fa+4*i)=*(const float4*)(Ar+k0+32+aks+4*i);
#pragma unroll
      for(int j=0;j<8;j++){
        int row=k0+32+2*(bkp+j);
        fb0[j]=Bp[(size_t)row*NHW+n0+bn];
        fb1[j]=Bp[(size_t)(row+1)*NHW+n0+bn];
      }
    }
#pragma unroll
    for(int s=0;s<2;s++){
      const int pb=s*8;
      unsigned a[4][4], b[4][2];
#pragma unroll
      for(int mt=0;mt<4;mt++){
        int mbx=wm*64+mt*16;
        a[mt][0]=Ahs[pb+tig][mbx+grp];   a[mt][1]=Ahs[pb+tig][mbx+grp+8];
        a[mt][2]=Ahs[pb+tig+4][mbx+grp]; a[mt][3]=Ahs[pb+tig+4][mbx+grp+8];
      }
#pragma unroll
      for(int nt=0;nt<4;nt++){
        int nb=wn*32+nt*8;
        b[nt][0]=Bhs[pb+tig][nb+grp]; b[nt][1]=Bhs[pb+tig+4][nb+grp];
      }
#pragma unroll
      for(int mt=0;mt<4;mt++)
#pragma unroll
        for(int nt=0;nt<4;nt++) mma16h(acc[mt][nt], a[mt], b[nt]);
    }
  }
  // epilogue: transpose 128m(c) x 128n(pix) tile through smem, write v2
  __syncthreads();
  __half (*st)[136] = (__half(*)[136])sbuf;
#pragma unroll
  for(int mt=0;mt<4;mt++)
#pragma unroll
    for(int half=0;half<2;half++){
      int m=wm*64+mt*16+grp+half*8;
#pragma unroll
      for(int nt=0;nt<4;nt++){
        int n=wn*32+nt*8+tig*2;
        st[n][m]  =__float2half(acc[mt][nt][half*2]);
        st[n+1][m]=__float2half(acc[mt][nt][half*2+1]);
      }
    }
  __syncthreads();
  __half2* v2p=(__half2*)(g_v2 + ((size_t)bI*NHW + n0)*NC + m0v);
#pragma unroll
  for(int i=0;i<32;i++){
    int lin=i*256+t, p=lin>>6, cj=lin&63;
    v2p[(size_t)p*(NC/2)+cj] = *(__half2*)&st[p][2*cj];
  }
}

// ---------------- fp32 96x96 transpose for q,k ------------------------------
__global__ __launch_bounds__(256) void transpose_qk(){
  __shared__ float s[96][97];
  const float* in  = blockIdx.y ? g_k  : g_q;
  float*       out = blockIdx.y ? g_kt : g_qt;
  size_t base=(size_t)blockIdx.x*NHW;
  int t=threadIdx.x;
#pragma unroll
  for(int i=0;i<36;i++){int idx=t+i*256; s[idx/96][idx%96]=in[base+idx];}
  __syncthreads();
#pragma unroll
  for(int i=0;i<36;i++){int idx=t+i*256; out[base+idx]=s[idx%96][idx/96];}
}

// ---------------- logits: split-fp16, fp16 E output -------------------------
__global__ __launch_bounds__(256) void logits_kernel(){
  __shared__ unsigned Qh[16][104], Ql[16][104], Kh[16][104], Kl[16][104];
  const int slab=blockIdx.x, mode=blockIdx.y;
  const int bI=slab/96, s=slab%96;
  const float* Qp=(mode? g_qt : g_q) + (size_t)bI*NIC*NHW + s*96;
  const float* Kp=(mode? g_kt : g_k) + (size_t)bI*NIC*NHW + s*96;
  __half* Ep=(mode? g_Ehh : g_Ewh) + (size_t)slab*NHW;
  const int t=threadIdx.x, lane=t&31, grp=lane>>2, tig=lane&3;
  const int warp=t>>5, wm=warp>>2, wn=warp&3;

  float acc[3][3][4];
#pragma unroll
  for(int i=0;i<3;i++)for(int j=0;j<3;j++)for(int r=0;r<4;r++) acc[i][j][r]=0.f;

  for(int c0=0;c0<NIC;c0+=32){
    if(c0) __syncthreads();
#pragma unroll
    for(int i=0;i<6;i++){
      int idx=t+i*256, p=idx/96, w=idx%96;
      int ch=c0+2*p;
      float q0=Qp[(size_t)ch*NHW+w],  q1=Qp[(size_t)(ch+1)*NHW+w];
      float k0v=Kp[(size_t)ch*NHW+w], k1v=Kp[(size_t)(ch+1)*NHW+w];
      unsigned hi,lo;
      split2(q0,q1,hi,lo); Qh[p][w]=hi; Ql[p][w]=lo;
      split2(k0v,k1v,hi,lo); Kh[p][w]=hi; Kl[p][w]=lo;
    }
    __syncthreads();
#pragma unroll
    for(int s2=0;s2<2;s2++){
      const int pb=s2*8;
      unsigned ah[3][4], al[3][4], bh[3][2], bl[3][2];
#pragma unroll
      for(int mt=0;mt<3;mt++){
        int mbx=wm*48+mt*16;
        ah[mt][0]=Qh[pb+tig][mbx+grp];   ah[mt][1]=Qh[pb+tig][mbx+grp+8];
        ah[mt][2]=Qh[pb+tig+4][mbx+grp]; ah[mt][3]=Qh[pb+tig+4][mbx+grp+8];
        al[mt][0]=Ql[pb+tig][mbx+grp];   al[mt][1]=Ql[pb+tig][mbx+grp+8];
        al[mt][2]=Ql[pb+tig+4][mbx+grp]; al[mt][3]=Ql[pb+tig+4][mbx+grp+8];
      }
#pragma unroll
      for(int nt=0;nt<3;nt++){
        int nb=wn*24+nt*8;
        bh[nt][0]=Kh[pb+tig][nb+grp]; bh[nt][1]=Kh[pb+tig+4][nb+grp];
        bl[nt][0]=Kl[pb+tig][nb+grp]; bl[nt][1]=Kl[pb+tig+4][nb+grp];
      }
#pragma unroll
      for(int mt=0;mt<3;mt++)
#pragma unroll
        for(int nt=0;nt<3;nt++){
          mma16h(acc[mt][nt], ah[mt], bh[nt]);
          mma16h(acc[mt][nt], al[mt], bh[nt]);
          mma16h(acc[mt][nt], ah[mt], bl[nt]);
        }
    }
  }
#pragma unroll
  for(int mt=0;mt<3;mt++)
#pragma unroll
    for(int half=0;half<2;half++){
      int row=wm*48+mt*16+grp+half*8;
#pragma unroll
      for(int nt=0;nt<3;nt++){
        int col=wn*24+nt*8+tig*2;
        *(__half2*)(Ep+(size_t)row*96+col)=
            __floats2half2_rn(acc[mt][nt][half*2],acc[mt][nt][half*2+1]);
      }
    }
}

// ---------------- fused 192-wide softmax (fp16 E in, fp16 A out) -----------
__global__ __launch_bounds__(256) void softmax_kernel(){
  const int warp=threadIdx.x>>5, lane=threadIdx.x&31;
  const int p=blockIdx.x*8+warp;
  const int bI=p/NHW, rem=p%NHW, h=rem/96, w=rem%96;
  const __half* ehp = g_Ehh + ((size_t)(bI*96+w)*96 + h)*96;
  const __half* ewp = g_Ewh + (size_t)p*96;
  __half* ahp = g_Ahh + ((size_t)(bI*96+w)*96 + h)*96;
  __half* awp = g_Awh + (size_t)p*96;
  float eh[3], ew[3], m=-1e30f;
#pragma unroll
  for(int j=0;j<3;j++){
    int g=lane+32*j;
    eh[j]=(g==h)? -1e30f : __half2float(ehp[g]);
    ew[j]=__half2float(ewp[g]);
    m=fmaxf(m,fmaxf(eh[j],ew[j]));
  }
#pragma unroll
  for(int o=16;o>0;o>>=1) m=fmaxf(m,__shfl_xor_sync(0xffffffffu,m,o));
  float sum=0.f;
#pragma unroll
  for(int j=0;j<3;j++){
    eh[j]=__expf(eh[j]-m); ew[j]=__expf(ew[j]-m); sum+=eh[j]+ew[j];
  }
#pragma unroll
  for(int o=16;o>0;o>>=1) sum+=__shfl_xor_sync(0xffffffffu,sum,o);
  float inv=1.f/sum;
#pragma unroll
  for(int j=0;j<3;j++){
    int g=lane+32*j;
    ahp[g]=__float2half((g==h)?0.f:eh[j]*inv);
    awp[g]=__float2half(ew[j]*inv);
  }
}

// ---------------- aggregation: o2 = A_slab(96x96) @ v_slab(96x512) ---------
// mode0 (row attention): plain stores into o2[b][h][w][c].
// mode1 (col attention): red.global.add.f16x2 into the SAME buffer at the
// transposed pixel address — combine's o2h input and its transpose vanish.
// mode1 is launched AFTER mode0 completes (separate kernel launches).
__global__ __launch_bounds__(256) void agg_v(int mode){
  __shared__ unsigned As[24][104];
  __shared__ unsigned Bs[24][264];
  const int nck=blockIdx.x, slab=blockIdx.y;
  const int bI=slab/96, s=slab%96, n0=nck*256;
  const __half* Ap=(mode? g_Ahh : g_Awh) + (size_t)slab*NHW;
  const __half* Bb = g_v2 + (mode ? ((size_t)bI*NHW + s)*NC : (size_t)slab*96*NC);
  const size_t rstride = mode ? (size_t)96*NC : (size_t)NC;
  __half* Op = g_o2 + (mode ? ((size_t)bI*NHW + s)*NC : (size_t)slab*96*NC);
  const size_t ostride = mode ? (size_t)96*NC : (size_t)NC;
  const int t=threadIdx.x, lane=t&31, grp=lane>>2, tig=lane&3;
  const int warp=t>>5, wm=warp>>2, wn=warp&3;

  float acc[3][8][4];
#pragma unroll
  for(int i=0;i<3;i++)for(int j=0;j<8;j++)for(int r=0;r<4;r++) acc[i][j][r]=0.f;

  for(int kc=0;kc<96;kc+=48){
    if(kc) __syncthreads();
#pragma unroll
    for(int i=0;i<9;i++){
      int idx=t+i*256, m=idx/24, kp=idx%24;
      As[kp][m]=*(const unsigned*)(Ap + (size_t)m*96 + kc + 2*kp);
    }
#pragma unroll
    for(int i=0;i<12;i++){
      int idx=t+i*256, kp=idx/128, nj=idx%128;
      const __half* r0=Bb + (size_t)(kc+2*kp)*rstride + n0 + 2*nj;
      unsigned u0=*(const unsigned*)r0;
      unsigned u1=*(const unsigned*)(r0+rstride);
      Bs[kp][2*nj]  =(u0&0xffffu)|(u1<<16);
      Bs[kp][2*nj+1]=(u0>>16)|(u1&0xffff0000u);
    }
    __syncthreads();
#pragma unroll
    for(int s2=0;s2<3;s2++){
      const int pb=s2*8;
      unsigned a[3][4], b[8][2];
#pragma unroll
      for(int mt=0;mt<3;mt++){
        int mbx=wm*48+mt*16;
        a[mt][0]=As[pb+tig][mbx+grp];   a[mt][1]=As[pb+tig][mbx+grp+8];
        a[mt][2]=As[pb+tig+4][mbx+grp]; a[mt][3]=As[pb+tig+4][mbx+grp+8];
      }
#pragma unroll
      for(int nt=0;nt<8;nt++){
        int nb=wn*64+nt*8;
        b[nt][0]=Bs[pb+tig][nb+grp]; b[nt][1]=Bs[pb+tig+4][nb+grp];
      }
#pragma unroll
      for(int mt=0;mt<3;mt++)
#pragma unroll
        for(int nt=0;nt<8;nt++) mma16h(acc[mt][nt], a[mt], b[nt]);
    }
  }
#pragma unroll
  for(int mt=0;mt<3;mt++)
#pragma unroll
    for(int half=0;half<2;half++){
      int m=wm*48+mt*16+grp+half*8;
#pragma unroll
      for(int nt=0;nt<8;nt++){
        int col=n0+wn*64+nt*8+tig*2;
        __half2 val=__floats2half2_rn(acc[mt][nt][half*2],acc[mt][nt][half*2+1]);
        __half2* dst=(__half2*)(Op + (size_t)m*ostride + col);
        if(mode==0) *dst=val;
        else        red_h2(dst,val);
      }
    }
}

// ---------------- combine: out = gamma*(o2 + bv) + x ------------------------
__global__ __launch_bounds__(256) void combine_kernel(
  const float* __restrict__ bv, const float* __restrict__ gamma,
  const float* __restrict__ x, float* __restrict__ out)
{
  __shared__ float s[96][65];
  const int c0=blockIdx.x*64, h=blockIdx.y, bI=blockIdx.z;
  const int t=threadIdx.x;
  const float gam=gamma[0];
#pragma unroll
  for(int i=0;i<12;i++){
    int idx=t+i*256, w=idx/32, cj=idx%32;
    __half2 aw=*(const __half2*)(g_o2 + ((size_t)(bI*96+h)*96+w)*NC + c0 + 2*cj);
    float2 fa=__half22float2(aw);
    s[w][2*cj]=fa.x; s[w][2*cj+1]=fa.y;
  }
  __syncthreads();
#pragma unroll
  for(int i=0;i<24;i++){
    int idx=t+i*256, c=idx/96, w=idx%96;
    size_t a=((size_t)bI*NC + c0+c)*NHW + (size_t)h*96 + w;
    out[a]=gam*(s[w][c]+bv[c0+c])+x[a];
  }
}

// ---------------- launch ----------------------------------------------------
extern "C" void kernel_launch(void* const* d_in, const int* in_sizes, int n_in,
                              void* d_out, int out_size){
  const float* x    =(const float*)d_in[0];
  const float* Wq   =(const float*)d_in[1];
  const float* bq   =(const float*)d_in[2];
  const float* Wk   =(const float*)d_in[3];
  const float* bk   =(const float*)d_in[4];
  const float* Wv   =(const float*)d_in[5];
  const float* bv   =(const float*)d_in[6];
  const float* gamma=(const float*)d_in[7];
  float* out=(float*)d_out;

  gemm_qk<<<dim3(NHW/128,NB),256>>>(x,Wq,bq,Wk,bk);
  gemm_v<<<dim3(NHW/128,4,NB),256>>>(x,Wv);
  transpose_qk<<<dim3(NB*NIC,2),256>>>();
  logits_kernel<<<dim3(NB*96,2),256>>>();
  softmax_kernel<<<NB*NHW/8,256>>>();
  agg_v<<<dim3(2,NB*96),256>>>(0);
  agg_v<<<dim3(2,NB*96),256>>>(1);
  combine_kernel<<<dim3(8,96,NB),256>>>(bv,gamma,x,out);
}